// round 1
// baseline (speedup 1.0000x reference)
#include <cuda_runtime.h>

#define B_   4
#define CI_  128
#define CO_  128
#define H_   128
#define W_   128
#define HW_  (H_*W_)
#define KK_  9
#define NPIX (B_*HW_)   // 65536
#define BN_EPS 0.001f

// ---------------- scratch (static device globals; no dynamic alloc) ----------------
__device__ float  g_x_nhwc[NPIX*CI_];     // x transposed to [b][h][w][ci]   (33.5 MB)
__device__ float  g_off[NPIX*18];         // offsets, pixel-major [px][18]   (4.7 MB)
__device__ float  g_wt[KK_*CI_*CO_];      // w_dcn transposed [tap][ci][co]  (576 KB)
__device__ float  g_out[NPIX*CO_];        // GEMM out, pixel-major [px][co]  (33.5 MB)
__device__ double g_sum[CO_];
__device__ double g_sumsq[CO_];
__device__ float  g_scale[CO_];
__device__ float  g_shift[CO_];

// ---------------- zero BN accumulators ----------------
__global__ void k_zero() {
    int t = threadIdx.x;
    if (t < CO_) { g_sum[t] = 0.0; g_sumsq[t] = 0.0; }
}

// ---------------- x: NCHW -> NHWC (tiled transpose) ----------------
__global__ void k_tr_x(const float* __restrict__ x) {
    __shared__ float sm[32][33];
    int b = blockIdx.z, ci0 = blockIdx.y * 32, hw0 = blockIdx.x * 32;
    int tx = threadIdx.x, ty = threadIdx.y;
#pragma unroll
    for (int i = 0; i < 4; ++i) {
        int ci = ci0 + ty + i * 8;
        sm[ty + i * 8][tx] = x[(b * CI_ + ci) * HW_ + hw0 + tx];
    }
    __syncthreads();
#pragma unroll
    for (int i = 0; i < 4; ++i) {
        int hw = hw0 + ty + i * 8;
        g_x_nhwc[(b * HW_ + hw) * CI_ + ci0 + tx] = sm[tx][ty + i * 8];
    }
}

// ---------------- w_dcn: [co][ci][tap] -> [tap][ci][co] ----------------
__global__ void k_tr_w(const float* __restrict__ w_dcn) {
    int idx = blockIdx.x * 256 + threadIdx.x;
    if (idx < KK_ * CI_ * CO_) {
        int tap = idx >> 14;
        int ci  = (idx >> 7) & 127;
        int co  = idx & 127;
        g_wt[idx] = w_dcn[(co * CI_ + ci) * KK_ + tap];
    }
}

// ---------------- offset conv: 3x3, 128 -> 18 channels ----------------
// one thread per pixel; weights in smem layout [tap][ci][20] (pad 18->20 for f4 align)
__global__ void k_off(const float* __restrict__ w_off, const float* __restrict__ b_off) {
    extern __shared__ float ws[];   // 9*128*20 floats = 92160 B
    int tid = threadIdx.x;
    for (int idx = tid; idx < 9 * 128 * 20; idx += 256) {
        int tap = idx / 2560;
        int r   = idx - tap * 2560;
        int ci  = r / 20;
        int c   = r - ci * 20;
        ws[idx] = (c < 18) ? w_off[(c * CI_ + ci) * KK_ + tap] : 0.f;
    }
    __syncthreads();

    int px = blockIdx.x * 256 + tid;
    int b = px >> 14, h = (px >> 7) & 127, w = px & 127;
    float acc[18];
#pragma unroll
    for (int c = 0; c < 18; ++c) acc[c] = b_off[c];

    for (int ky = 0; ky < 3; ++ky) {
        int y = h - 1 + ky;
        if ((unsigned)y >= (unsigned)H_) continue;
        for (int kx = 0; kx < 3; ++kx) {
            int x = w - 1 + kx;
            if ((unsigned)x >= (unsigned)W_) continue;
            int tap = ky * 3 + kx;
            const float4* xin = (const float4*)&g_x_nhwc[((b * H_ + y) * W_ + x) * CI_];
            const float* wt = &ws[tap * 2560];
#pragma unroll 4
            for (int ci4 = 0; ci4 < 32; ++ci4) {
                float4 xv = xin[ci4];
#pragma unroll
                for (int j = 0; j < 4; ++j) {
                    float v = (j == 0) ? xv.x : (j == 1) ? xv.y : (j == 2) ? xv.z : xv.w;
                    const float4* wp = (const float4*)&wt[(ci4 * 4 + j) * 20];
                    float4 w0 = wp[0], w1 = wp[1], w2 = wp[2], w3 = wp[3], w4 = wp[4];
                    acc[0]  = fmaf(w0.x, v, acc[0]);  acc[1]  = fmaf(w0.y, v, acc[1]);
                    acc[2]  = fmaf(w0.z, v, acc[2]);  acc[3]  = fmaf(w0.w, v, acc[3]);
                    acc[4]  = fmaf(w1.x, v, acc[4]);  acc[5]  = fmaf(w1.y, v, acc[5]);
                    acc[6]  = fmaf(w1.z, v, acc[6]);  acc[7]  = fmaf(w1.w, v, acc[7]);
                    acc[8]  = fmaf(w2.x, v, acc[8]);  acc[9]  = fmaf(w2.y, v, acc[9]);
                    acc[10] = fmaf(w2.z, v, acc[10]); acc[11] = fmaf(w2.w, v, acc[11]);
                    acc[12] = fmaf(w3.x, v, acc[12]); acc[13] = fmaf(w3.y, v, acc[13]);
                    acc[14] = fmaf(w3.z, v, acc[14]); acc[15] = fmaf(w3.w, v, acc[15]);
                    acc[16] = fmaf(w4.x, v, acc[16]); acc[17] = fmaf(w4.y, v, acc[17]);
                }
            }
        }
    }
#pragma unroll
    for (int c = 0; c < 18; ++c) g_off[px * 18 + c] = acc[c];
}

// ---------------- fused deformable sampling + implicit GEMM + BN partials --------
// block: 256 threads, 64 pixels x 128 CO. thread: tc=tid&31 (4 co), tp=tid>>5 (8 px)
__global__ void k_main() {
    extern __shared__ float smem[];
    float* sS = smem;                       // [64][128] sampled tile (8192 f)
    float* sW = smem + 8192;                // [128][128] weight tile (16384 f)
    int*   sA = (int*)(smem + 24576);       // [4][64] corner base addrs
    float* sB = (float*)(sA + 256);         // [4][64] corner bilinear weights

    int tid = threadIdx.x;
    int tc = tid & 31, tp = tid >> 5;
    int px0 = blockIdx.x * 64;

    float4 acc[8];
#pragma unroll
    for (int j = 0; j < 8; ++j) acc[j] = make_float4(0.f, 0.f, 0.f, 0.f);

    for (int k = 0; k < 9; ++k) {
        __syncthreads();   // prev iter's GEMM done before overwriting sW/sA/sB
        // weight tile for this tap (coalesced float4)
        {
            const float4* gw = (const float4*)(g_wt + k * 16384);
            float4* sW4 = (float4*)sW;
#pragma unroll
            for (int i = 0; i < 16; ++i) sW4[tid + i * 256] = gw[tid + i * 256];
        }
        // per-pixel sampling params
        if (tid < 64) {
            int px = px0 + tid;
            int b = px >> 14, h = (px >> 7) & 127, w = px & 127;
            int ky = k / 3, kx = k - ky * 3;
            float dy = g_off[px * 18 + 2 * k];
            float dx = g_off[px * 18 + 2 * k + 1];
            float ysf = (float)(h - 1 + ky) + dy;
            float xsf = (float)(w - 1 + kx) + dx;
            float fy = floorf(ysf), fx = floorf(xsf);
            float wy = ysf - fy, wx = xsf - fx;
            int iy0 = (int)fy, ix0 = (int)fx;
            int iy1 = iy0 + 1, ix1 = ix0 + 1;
            float my0 = (iy0 >= 0 && iy0 < H_) ? 1.f : 0.f;
            float my1 = (iy1 >= 0 && iy1 < H_) ? 1.f : 0.f;
            float mx0 = (ix0 >= 0 && ix0 < W_) ? 1.f : 0.f;
            float mx1 = (ix1 >= 0 && ix1 < W_) ? 1.f : 0.f;
            int cy0 = min(H_ - 1, max(0, iy0)), cy1 = min(H_ - 1, max(0, iy1));
            int cx0 = min(W_ - 1, max(0, ix0)), cx1 = min(W_ - 1, max(0, ix1));
            int base = b * HW_;
            sA[tid]       = (base + cy0 * W_ + cx0) * CI_;
            sA[64 + tid]  = (base + cy0 * W_ + cx1) * CI_;
            sA[128 + tid] = (base + cy1 * W_ + cx0) * CI_;
            sA[192 + tid] = (base + cy1 * W_ + cx1) * CI_;
            sB[tid]       = (1.f - wy) * (1.f - wx) * my0 * mx0;
            sB[64 + tid]  = (1.f - wy) * wx * my0 * mx1;
            sB[128 + tid] = wy * (1.f - wx) * my1 * mx0;
            sB[192 + tid] = wy * wx * my1 * mx1;
        }
        __syncthreads();
        // bilinear sampling: build S[64][128]; one warp per pixel, lane = 4 channels
#pragma unroll
        for (int i = 0; i < 8; ++i) {
            int task = tid + i * 256;
            int p  = task >> 5;
            int c4 = (task & 31) << 2;
            int a00 = sA[p], a01 = sA[64 + p], a10 = sA[128 + p], a11 = sA[192 + p];
            float w00 = sB[p], w01 = sB[64 + p], w10 = sB[128 + p], w11 = sB[192 + p];
            float4 v00 = *(const float4*)(g_x_nhwc + a00 + c4);
            float4 v01 = *(const float4*)(g_x_nhwc + a01 + c4);
            float4 v10 = *(const float4*)(g_x_nhwc + a10 + c4);
            float4 v11 = *(const float4*)(g_x_nhwc + a11 + c4);
            float4 s;
            s.x = fmaf(v11.x, w11, fmaf(v10.x, w10, fmaf(v01.x, w01, v00.x * w00)));
            s.y = fmaf(v11.y, w11, fmaf(v10.y, w10, fmaf(v01.y, w01, v00.y * w00)));
            s.z = fmaf(v11.z, w11, fmaf(v10.z, w10, fmaf(v01.z, w01, v00.z * w00)));
            s.w = fmaf(v11.w, w11, fmaf(v10.w, w10, fmaf(v01.w, w01, v00.w * w00)));
            *(float4*)(sS + p * 128 + c4) = s;
        }
        __syncthreads();
        // GEMM: acc[8px][4co] += S[p][ci] * W[ci][co]
        const float4* sW4 = (const float4*)sW;
#pragma unroll 2
        for (int ci = 0; ci < 128; ++ci) {
            float4 b4 = sW4[ci * 32 + tc];
#pragma unroll
            for (int j = 0; j < 8; ++j) {
                float a = sS[(tp * 8 + j) * 128 + ci];
                acc[j].x = fmaf(a, b4.x, acc[j].x);
                acc[j].y = fmaf(a, b4.y, acc[j].y);
                acc[j].z = fmaf(a, b4.z, acc[j].z);
                acc[j].w = fmaf(a, b4.w, acc[j].w);
            }
        }
    }

    // epilogue: store out (pixel-major, coalesced float4)
#pragma unroll
    for (int j = 0; j < 8; ++j) {
        int px = px0 + tp * 8 + j;
        *(float4*)(g_out + px * CO_ + tc * 4) = acc[j];
    }
    // BN partials
    float4 s = make_float4(0.f, 0.f, 0.f, 0.f);
    float4 q = make_float4(0.f, 0.f, 0.f, 0.f);
#pragma unroll
    for (int j = 0; j < 8; ++j) {
        s.x += acc[j].x; q.x = fmaf(acc[j].x, acc[j].x, q.x);
        s.y += acc[j].y; q.y = fmaf(acc[j].y, acc[j].y, q.y);
        s.z += acc[j].z; q.z = fmaf(acc[j].z, acc[j].z, q.z);
        s.w += acc[j].w; q.w = fmaf(acc[j].w, acc[j].w, q.w);
    }
    __syncthreads();            // done reading sS; reuse as reduction scratch
    float* rs = sS;             // [8][128]
    float* rq = sS + 1024;      // [8][128]
    rs[tp * 128 + tc * 4 + 0] = s.x; rs[tp * 128 + tc * 4 + 1] = s.y;
    rs[tp * 128 + tc * 4 + 2] = s.z; rs[tp * 128 + tc * 4 + 3] = s.w;
    rq[tp * 128 + tc * 4 + 0] = q.x; rq[tp * 128 + tc * 4 + 1] = q.y;
    rq[tp * 128 + tc * 4 + 2] = q.z; rq[tp * 128 + tc * 4 + 3] = q.w;
    __syncthreads();
    if (tid < 128) {
        float ss = 0.f, qq = 0.f;
#pragma unroll
        for (int t = 0; t < 8; ++t) { ss += rs[t * 128 + tid]; qq += rq[t * 128 + tid]; }
        atomicAdd(&g_sum[tid], (double)ss);
        atomicAdd(&g_sumsq[tid], (double)qq);
    }
}

// ---------------- BN finalize: per-channel scale/shift ----------------
__global__ void k_fin(const float* __restrict__ gamma, const float* __restrict__ beta) {
    int c = threadIdx.x;
    if (c < CO_) {
        double N = (double)NPIX;
        double mean = g_sum[c] / N;
        double var  = g_sumsq[c] / N - mean * mean;
        float a = gamma[c] * rsqrtf((float)var + BN_EPS);
        g_scale[c] = a;
        g_shift[c] = beta[c] - (float)mean * a;
    }
}

// ---------------- apply BN + ReLU + transpose [px][co] -> NCHW ----------------
__global__ void k_apply(float* __restrict__ out) {
    __shared__ float sm[32][33];
    int b = blockIdx.z, co0 = blockIdx.y * 32, hw0 = blockIdx.x * 32;
    int tx = threadIdx.x, ty = threadIdx.y;
#pragma unroll
    for (int i = 0; i < 4; ++i) {
        int hw = hw0 + ty + i * 8;
        sm[ty + i * 8][tx] = g_out[(b * HW_ + hw) * CO_ + co0 + tx];
    }
    __syncthreads();
#pragma unroll
    for (int i = 0; i < 4; ++i) {
        int co = co0 + ty + i * 8;
        float a = g_scale[co], sh = g_shift[co];
        float v = fmaf(sm[tx][ty + i * 8], a, sh);
        out[(b * CO_ + co) * HW_ + hw0 + tx] = fmaxf(v, 0.f);
    }
}

// ---------------- launch ----------------
extern "C" void kernel_launch(void* const* d_in, const int* in_sizes, int n_in,
                              void* d_out, int out_size) {
    const float* x      = (const float*)d_in[0];
    const float* w_off  = (const float*)d_in[1];
    const float* b_off  = (const float*)d_in[2];
    const float* w_dcn  = (const float*)d_in[3];
    const float* gamma  = (const float*)d_in[4];
    const float* beta   = (const float*)d_in[5];
    float* out = (float*)d_out;

    cudaFuncSetAttribute(k_off,  cudaFuncAttributeMaxDynamicSharedMemorySize, 92160);
    cudaFuncSetAttribute(k_main, cudaFuncAttributeMaxDynamicSharedMemorySize, 100352);

    dim3 tb(32, 8);
    k_zero<<<1, 128>>>();
    k_tr_x<<<dim3(512, 4, B_), tb>>>(x);
    k_tr_w<<<576, 256>>>(w_dcn);
    k_off<<<256, 256, 92160>>>(w_off, b_off);
    k_main<<<1024, 256, 100352>>>();
    k_fin<<<1, 128>>>(gamma, beta);
    k_apply<<<dim3(512, 4, B_), tb>>>(out);
}

// round 3
// speedup vs baseline: 1.1835x; 1.1835x over previous
#include <cuda_runtime.h>
#include <cuda_bf16.h>
#include <cstdint>

#define B_   4
#define CI_  128
#define CO_  128
#define H_   128
#define W_   128
#define HW_  (H_*W_)
#define KK_  9
#define NPIX (B_*HW_)   // 65536
#define BN_EPS 0.001f

// ---------------- scratch ----------------
__device__ float  g_x_nhwc[NPIX*CI_];               // [b][h][w][ci]
__device__ float  g_off[NPIX*18];                   // [px][18]
__device__ __nv_bfloat16 g_wb_hi[KK_*CO_*CI_];      // [tap][co][ci] bf16 hi
__device__ __nv_bfloat16 g_wb_lo[KK_*CO_*CI_];      // [tap][co][ci] bf16 lo
__device__ float  g_out[NPIX*CO_];                  // [px][co]
__device__ double g_sum[CO_];
__device__ double g_sumsq[CO_];
__device__ float  g_scale[CO_];
__device__ float  g_shift[CO_];

__device__ __forceinline__ uint32_t smem_u32(const void* p) {
    uint32_t a;
    asm("{ .reg .u64 t; cvta.to.shared.u64 t, %1; cvt.u32.u64 %0, t; }" : "=r"(a) : "l"(p));
    return a;
}

// ---------------- zero BN accumulators ----------------
__global__ void k_zero() {
    int t = threadIdx.x;
    if (t < CO_) { g_sum[t] = 0.0; g_sumsq[t] = 0.0; }
}

// ---------------- x: NCHW -> NHWC ----------------
__global__ void k_tr_x(const float* __restrict__ x) {
    __shared__ float sm[32][33];
    int b = blockIdx.z, ci0 = blockIdx.y * 32, hw0 = blockIdx.x * 32;
    int tx = threadIdx.x, ty = threadIdx.y;
#pragma unroll
    for (int i = 0; i < 4; ++i) {
        int ci = ci0 + ty + i * 8;
        sm[ty + i * 8][tx] = x[(b * CI_ + ci) * HW_ + hw0 + tx];
    }
    __syncthreads();
#pragma unroll
    for (int i = 0; i < 4; ++i) {
        int hw = hw0 + ty + i * 8;
        g_x_nhwc[(b * HW_ + hw) * CI_ + ci0 + tx] = sm[tx][ty + i * 8];
    }
}

// ---------------- w_dcn -> [tap][co][ci] bf16 hi/lo ----------------
__global__ void k_tr_w2(const float* __restrict__ w_dcn) {
    int idx = blockIdx.x * 256 + threadIdx.x;
    if (idx >= KK_ * CO_ * CI_) return;
    int tap = idx >> 14;
    int r   = idx & 16383;
    int co  = r >> 7;
    int ci  = r & 127;
    float w = w_dcn[(co * CI_ + ci) * KK_ + tap];
    __nv_bfloat16 hi = __float2bfloat16(w);
    float res = w - __bfloat162float(hi);
    __nv_bfloat16 lo = __float2bfloat16(res);
    g_wb_hi[tap * 16384 + co * 128 + ci] = hi;
    g_wb_lo[tap * 16384 + co * 128 + ci] = lo;
}

// ---------------- offset conv v2: smem input tiles, coalesced ----------------
__global__ void __launch_bounds__(256, 1) k_off2(const float* __restrict__ x,
                                                 const float* __restrict__ w_off,
                                                 const float* __restrict__ b_off) {
    extern __shared__ float dsm[];
    float* ws   = dsm;            // 9*128*20 = 23040 floats
    float* tile = dsm + 23040;    // 32*4*128 = 16384 floats

    int tid = threadIdx.x;
    int blk = blockIdx.x;
    int b  = blk >> 6;
    int y0 = (blk & 63) * 2;
    int rsel = tid >> 7;
    int xp   = tid & 127;

    for (int idx = tid; idx < 9 * 128 * 20; idx += 256) {
        int tap = idx / 2560;
        int r   = idx - tap * 2560;
        int ci  = r / 20;
        int c   = r - ci * 20;
        ws[idx] = (c < 18) ? w_off[(c * CI_ + ci) * KK_ + tap] : 0.f;
    }

    float acc[18];
#pragma unroll
    for (int c = 0; c < 18; ++c) acc[c] = b_off[c];

    for (int c0 = 0; c0 < 128; c0 += 32) {
        __syncthreads();
#pragma unroll
        for (int t = 0; t < 64; ++t) {
            int idx = tid + t * 256;
            int ci  = idx >> 9;
            int rem = idx & 511;
            int wy  = rem >> 7;
            int xx  = rem & 127;
            int y   = y0 - 1 + wy;
            float v = 0.f;
            if ((unsigned)y < (unsigned)H_)
                v = x[((b * CI_ + c0 + ci) * H_ + y) * W_ + xx];
            tile[idx] = v;
        }
        __syncthreads();

        for (int ky = 0; ky < 3; ++ky) {
            int yl = rsel + ky;
            for (int kx = 0; kx < 3; ++kx) {
                int xc = xp - 1 + kx;
                if ((unsigned)xc >= (unsigned)W_) continue;
                int tap = ky * 3 + kx;
                const float* tbase = &tile[yl * 128 + xc];
                const float* wbase = &ws[tap * 2560 + c0 * 20];
#pragma unroll 2
                for (int ci = 0; ci < 32; ++ci) {
                    float v = tbase[ci * 512];
                    const float4* wp = (const float4*)&wbase[ci * 20];
                    float4 w0 = wp[0], w1 = wp[1], w2 = wp[2], w3 = wp[3], w4 = wp[4];
                    acc[0]  = fmaf(w0.x, v, acc[0]);  acc[1]  = fmaf(w0.y, v, acc[1]);
                    acc[2]  = fmaf(w0.z, v, acc[2]);  acc[3]  = fmaf(w0.w, v, acc[3]);
                    acc[4]  = fmaf(w1.x, v, acc[4]);  acc[5]  = fmaf(w1.y, v, acc[5]);
                    acc[6]  = fmaf(w1.z, v, acc[6]);  acc[7]  = fmaf(w1.w, v, acc[7]);
                    acc[8]  = fmaf(w2.x, v, acc[8]);  acc[9]  = fmaf(w2.y, v, acc[9]);
                    acc[10] = fmaf(w2.z, v, acc[10]); acc[11] = fmaf(w2.w, v, acc[11]);
                    acc[12] = fmaf(w3.x, v, acc[12]); acc[13] = fmaf(w3.y, v, acc[13]);
                    acc[14] = fmaf(w3.z, v, acc[14]); acc[15] = fmaf(w3.w, v, acc[15]);
                    acc[16] = fmaf(w4.x, v, acc[16]); acc[17] = fmaf(w4.y, v, acc[17]);
                }
            }
        }
    }
    int px = b * HW_ + (y0 + rsel) * W_ + xp;
#pragma unroll
    for (int c = 0; c < 18; ++c) g_off[px * 18 + c] = acc[c];
}

// ---------------- main: sampling + HMMA (mma.sync bf16 hi/lo split) ------------
// CTA 128px x 128co, 256 thr = 8 warps (2 m x 4 n), warp tile 64px x 32co.
// smem rows: 272B stride (17*16B -> conflict-free ldmatrix)
#define RS    272
#define SM_AHI 0
#define SM_ALO 34816
#define SM_BHI 69632
#define SM_BLO 104448
#define SM_PA  139264
#define SM_PB  141312
#define SM_TOT 143360

__device__ __forceinline__ void ldm_x4(uint32_t* r, uint32_t a) {
    asm volatile("ldmatrix.sync.aligned.m8n8.x4.shared.b16 {%0,%1,%2,%3}, [%4];"
                 : "=r"(r[0]), "=r"(r[1]), "=r"(r[2]), "=r"(r[3]) : "r"(a));
}
__device__ __forceinline__ void ldm_x2(uint32_t* r, uint32_t a) {
    asm volatile("ldmatrix.sync.aligned.m8n8.x2.shared.b16 {%0,%1}, [%2];"
                 : "=r"(r[0]), "=r"(r[1]) : "r"(a));
}
__device__ __forceinline__ void mma_bf16(float* c, const uint32_t* a, const uint32_t* b) {
    asm volatile(
        "mma.sync.aligned.m16n8k16.row.col.f32.bf16.bf16.f32 "
        "{%0,%1,%2,%3}, {%4,%5,%6,%7}, {%8,%9}, {%0,%1,%2,%3};"
        : "+f"(c[0]), "+f"(c[1]), "+f"(c[2]), "+f"(c[3])
        : "r"(a[0]), "r"(a[1]), "r"(a[2]), "r"(a[3]), "r"(b[0]), "r"(b[1]));
}

__global__ void __launch_bounds__(256, 1) k_mainH() {
    extern __shared__ char sb[];
    uint32_t sbase = smem_u32(sb);

    int tid = threadIdx.x;
    int wid = tid >> 5, lid = tid & 31;
    int wm = wid >> 2, wn = wid & 3;
    int px0 = blockIdx.x * 128;

    int*   sA = (int*)(sb + SM_PA);
    float* sB = (float*)(sb + SM_PB);

    float acc[4][4][4];
#pragma unroll
    for (int mi = 0; mi < 4; ++mi)
#pragma unroll
        for (int ni = 0; ni < 4; ++ni)
#pragma unroll
            for (int j = 0; j < 4; ++j) acc[mi][ni][j] = 0.f;

    // precomputed ldmatrix lane addresses (offsets within tile)
    uint32_t a_lane = (uint32_t)(wm * 64 + (lid & 15)) * RS + ((lid >> 4) << 4);
    uint32_t b_lane = (uint32_t)(wn * 32 + (lid & 7)) * RS + (((lid >> 3) & 1) << 4);

    for (int k = 0; k < 9; ++k) {
        __syncthreads();   // prev MMA done before overwriting tiles
        // ---- B tiles (hi/lo), 272B-stride rows ----
        {
            int co = tid >> 1, half = tid & 1;
            const uint4* srch = (const uint4*)((const char*)(g_wb_hi + k * 16384 + co * 128) + half * 128);
            const uint4* srcl = (const uint4*)((const char*)(g_wb_lo + k * 16384 + co * 128) + half * 128);
            uint4* dsth = (uint4*)(sb + SM_BHI + co * RS + half * 128);
            uint4* dstl = (uint4*)(sb + SM_BLO + co * RS + half * 128);
#pragma unroll
            for (int t = 0; t < 8; ++t) { dsth[t] = srch[t]; dstl[t] = srcl[t]; }
        }
        // ---- sampling params ----
        if (tid < 128) {
            int px = px0 + tid;
            int b = px >> 14, h = (px >> 7) & 127, w = px & 127;
            int ky = k / 3, kx = k - ky * 3;
            float dy = g_off[px * 18 + 2 * k];
            float dx = g_off[px * 18 + 2 * k + 1];
            float ysf = (float)(h - 1 + ky) + dy;
            float xsf = (float)(w - 1 + kx) + dx;
            float fy = floorf(ysf), fx = floorf(xsf);
            float wy = ysf - fy, wx = xsf - fx;
            int iy0 = (int)fy, ix0 = (int)fx;
            int iy1 = iy0 + 1, ix1 = ix0 + 1;
            float my0 = (iy0 >= 0 && iy0 < H_) ? 1.f : 0.f;
            float my1 = (iy1 >= 0 && iy1 < H_) ? 1.f : 0.f;
            float mx0 = (ix0 >= 0 && ix0 < W_) ? 1.f : 0.f;
            float mx1 = (ix1 >= 0 && ix1 < W_) ? 1.f : 0.f;
            int cy0 = min(H_ - 1, max(0, iy0)), cy1 = min(H_ - 1, max(0, iy1));
            int cx0 = min(W_ - 1, max(0, ix0)), cx1 = min(W_ - 1, max(0, ix1));
            int base = b * HW_;
            sA[tid]       = (base + cy0 * W_ + cx0) * CI_;
            sA[128 + tid] = (base + cy0 * W_ + cx1) * CI_;
            sA[256 + tid] = (base + cy1 * W_ + cx0) * CI_;
            sA[384 + tid] = (base + cy1 * W_ + cx1) * CI_;
            sB[tid]       = (1.f - wy) * (1.f - wx) * my0 * mx0;
            sB[128 + tid] = (1.f - wy) * wx * my0 * mx1;
            sB[256 + tid] = wy * (1.f - wx) * my1 * mx0;
            sB[384 + tid] = wy * wx * my1 * mx1;
        }
        __syncthreads();

        // ---- sampling: warp per pixel, lane = 4 channels; bf16 hi/lo to A tiles ----
#pragma unroll 2
        for (int i = 0; i < 16; ++i) {
            int p  = i * 8 + wid;
            int c4 = lid * 4;
            int a00 = sA[p], a01 = sA[128 + p], a10 = sA[256 + p], a11 = sA[384 + p];
            float w00 = sB[p], w01 = sB[128 + p], w10 = sB[256 + p], w11 = sB[384 + p];
            float4 v00 = *(const float4*)(g_x_nhwc + a00 + c4);
            float4 v01 = *(const float4*)(g_x_nhwc + a01 + c4);
            float4 v10 = *(const float4*)(g_x_nhwc + a10 + c4);
            float4 v11 = *(const float4*)(g_x_nhwc + a11 + c4);
            float4 s;
            s.x = fmaf(v11.x, w11, fmaf(v10.x, w10, fmaf(v01.x, w01, v00.x * w00)));
            s.y = fmaf(v11.y, w11, fmaf(v10.y, w10, fmaf(v01.y, w01, v00.y * w00)));
            s.z = fmaf(v11.z, w11, fmaf(v10.z, w10, fmaf(v01.z, w01, v00.z * w00)));
            s.w = fmaf(v11.w, w11, fmaf(v10.w, w10, fmaf(v01.w, w01, v00.w * w00)));

            __nv_bfloat16 h0 = __float2bfloat16(s.x), h1 = __float2bfloat16(s.y);
            __nv_bfloat16 h2 = __float2bfloat16(s.z), h3 = __float2bfloat16(s.w);
            __nv_bfloat16 l0 = __float2bfloat16(s.x - __bfloat162float(h0));
            __nv_bfloat16 l1 = __float2bfloat16(s.y - __bfloat162float(h1));
            __nv_bfloat16 l2 = __float2bfloat16(s.z - __bfloat162float(h2));
            __nv_bfloat16 l3 = __float2bfloat16(s.w - __bfloat162float(h3));
            uint2 hp, lp;
            hp.x = ((uint32_t)__bfloat16_as_ushort(h1) << 16) | __bfloat16_as_ushort(h0);
            hp.y = ((uint32_t)__bfloat16_as_ushort(h3) << 16) | __bfloat16_as_ushort(h2);
            lp.x = ((uint32_t)__bfloat16_as_ushort(l1) << 16) | __bfloat16_as_ushort(l0);
            lp.y = ((uint32_t)__bfloat16_as_ushort(l3) << 16) | __bfloat16_as_ushort(l2);
            uint32_t off = (uint32_t)p * RS + (uint32_t)(c4 * 2);
            *(uint2*)(sb + SM_AHI + off) = hp;
            *(uint2*)(sb + SM_ALO + off) = lp;
        }
        __syncthreads();

        // ---- warp MMA: acc += Ah*Bh + Ah*Bl + Al*Bh ----
#pragma unroll
        for (int ks = 0; ks < 8; ++ks) {
            uint32_t kb = (uint32_t)ks * 32;
            uint32_t bh[4][2], bl[4][2];
#pragma unroll
            for (int ni = 0; ni < 4; ++ni) {
                uint32_t ba = sbase + b_lane + (uint32_t)(ni * 8) * RS + kb;
                ldm_x2(bh[ni], SM_BHI + ba);
                ldm_x2(bl[ni], SM_BLO + ba);
            }
#pragma unroll
            for (int mi = 0; mi < 4; ++mi) {
                uint32_t aa = sbase + a_lane + (uint32_t)(mi * 16) * RS + kb;
                uint32_t ah[4], al[4];
                ldm_x4(ah, SM_AHI + aa);
                ldm_x4(al, SM_ALO + aa);
#pragma unroll
                for (int ni = 0; ni < 4; ++ni) {
                    mma_bf16(acc[mi][ni], ah, bh[ni]);
                    mma_bf16(acc[mi][ni], ah, bl[ni]);
                    mma_bf16(acc[mi][ni], al, bh[ni]);
                }
            }
        }
    }

    // ---- epilogue: acc -> g_out [px][co] ----
    int rofs = lid >> 2, cofs = (lid & 3) * 2;
#pragma unroll
    for (int mi = 0; mi < 4; ++mi) {
        int pxa = px0 + wm * 64 + mi * 16 + rofs;
#pragma unroll
        for (int ni = 0; ni < 4; ++ni) {
            int co = wn * 32 + ni * 8 + cofs;
            *(float2*)(g_out + pxa * CO_ + co)       = make_float2(acc[mi][ni][0], acc[mi][ni][1]);
            *(float2*)(g_out + (pxa + 8) * CO_ + co) = make_float2(acc[mi][ni][2], acc[mi][ni][3]);
        }
    }
}

// ---------------- BN reduction over g_out ----------------
__global__ void k_bnred() {
    __shared__ float red[2048];
    int tid = threadIdx.x;
    int tc = tid & 31, tp = tid >> 5;
    int px0 = blockIdx.x * 128;
    float4 s = make_float4(0.f, 0.f, 0.f, 0.f);
    float4 q = make_float4(0.f, 0.f, 0.f, 0.f);
#pragma unroll
    for (int r = 0; r < 16; ++r) {
        int px = px0 + tp * 16 + r;
        float4 v = *(const float4*)(g_out + px * CO_ + tc * 4);
        s.x += v.x; q.x = fmaf(v.x, v.x, q.x);
        s.y += v.y; q.y = fmaf(v.y, v.y, q.y);
        s.z += v.z; q.z = fmaf(v.z, v.z, q.z);
        s.w += v.w; q.w = fmaf(v.w, v.w, q.w);
    }
    float* rs = red;
    float* rq = red + 1024;
    rs[tp * 128 + tc * 4 + 0] = s.x; rs[tp * 128 + tc * 4 + 1] = s.y;
    rs[tp * 128 + tc * 4 + 2] = s.z; rs[tp * 128 + tc * 4 + 3] = s.w;
    rq[tp * 128 + tc * 4 + 0] = q.x; rq[tp * 128 + tc * 4 + 1] = q.y;
    rq[tp * 128 + tc * 4 + 2] = q.z; rq[tp * 128 + tc * 4 + 3] = q.w;
    __syncthreads();
    if (tid < 128) {
        float ss = 0.f, qq = 0.f;
#pragma unroll
        for (int t = 0; t < 8; ++t) { ss += rs[t * 128 + tid]; qq += rq[t * 128 + tid]; }
        atomicAdd(&g_sum[tid], (double)ss);
        atomicAdd(&g_sumsq[tid], (double)qq);
    }
}

// ---------------- BN finalize ----------------
__global__ void k_fin(const float* __restrict__ gamma, const float* __restrict__ beta) {
    int c = threadIdx.x;
    if (c < CO_) {
        double N = (double)NPIX;
        double mean = g_sum[c] / N;
        double var  = g_sumsq[c] / N - mean * mean;
        float a = gamma[c] * rsqrtf((float)var + BN_EPS);
        g_scale[c] = a;
        g_shift[c] = beta[c] - (float)mean * a;
    }
}

// ---------------- apply BN + ReLU + transpose [px][co] -> NCHW ----------------
__global__ void k_apply(float* __restrict__ out) {
    __shared__ float sm[32][33];
    int b = blockIdx.z, co0 = blockIdx.y * 32, hw0 = blockIdx.x * 32;
    int tx = threadIdx.x, ty = threadIdx.y;
#pragma unroll
    for (int i = 0; i < 4; ++i) {
        int hw = hw0 + ty + i * 8;
        sm[ty + i * 8][tx] = g_out[(b * HW_ + hw) * CO_ + co0 + tx];
    }
    __syncthreads();
#pragma unroll
    for (int i = 0; i < 4; ++i) {
        int co = co0 + ty + i * 8;
        float a = g_scale[co], sh = g_shift[co];
        float v = fmaf(sm[tx][ty + i * 8], a, sh);
        out[(b * CO_ + co) * HW_ + hw0 + tx] = fmaxf(v, 0.f);
    }
}

// ---------------- launch ----------------
extern "C" void kernel_launch(void* const* d_in, const int* in_sizes, int n_in,
                              void* d_out, int out_size) {
    const float* x      = (const float*)d_in[0];
    const float* w_off  = (const float*)d_in[1];
    const float* b_off  = (const float*)d_in[2];
    const float* w_dcn  = (const float*)d_in[3];
    const float* gamma  = (const float*)d_in[4];
    const float* beta   = (const float*)d_in[5];
    float* out = (float*)d_out;

    cudaFuncSetAttribute(k_off2,  cudaFuncAttributeMaxDynamicSharedMemorySize, 157696);
    cudaFuncSetAttribute(k_mainH, cudaFuncAttributeMaxDynamicSharedMemorySize, SM_TOT);

    dim3 tb(32, 8);
    k_zero<<<1, 128>>>();
    k_tr_x<<<dim3(512, 4, B_), tb>>>(x);
    k_tr_w2<<<576, 256>>>(w_dcn);
    k_off2<<<256, 256, 157696>>>(x, w_off, b_off);
    k_mainH<<<512, 256, SM_TOT>>>();
    k_bnred<<<512, 256>>>();
    k_fin<<<1, 128>>>(gamma, beta);
    k_apply<<<dim3(512, 4, B_), tb>>>(out);
}

// round 4
// speedup vs baseline: 1.2757x; 1.0778x over previous
#include <cuda_runtime.h>
#include <cuda_bf16.h>
#include <cstdint>

#define B_   4
#define CI_  128
#define CO_  128
#define H_   128
#define W_   128
#define HW_  (H_*W_)
#define KK_  9
#define NPIX (B_*HW_)   // 65536
#define BN_EPS 0.001f

// ---------------- scratch ----------------
__device__ float  g_x_nhwc[NPIX*CI_];               // [b][h][w][ci]
__device__ float  g_off[NPIX*18];                   // [px][18]
__device__ __nv_bfloat16 g_wb_hi[KK_*CO_*CI_];      // [tap][co][ci] bf16 hi
__device__ __nv_bfloat16 g_wb_lo[KK_*CO_*CI_];      // [tap][co][ci] bf16 lo
__device__ __nv_bfloat16 g_wo_hi[KK_*32*CI_];       // offset conv w: [tap][co32][ci]
__device__ __nv_bfloat16 g_wo_lo[KK_*32*CI_];
__device__ float  g_out[NPIX*CO_];                  // [px][co]
__device__ double g_sum[CO_];
__device__ double g_sumsq[CO_];
__device__ float  g_scale[CO_];
__device__ float  g_shift[CO_];

__device__ __forceinline__ uint32_t smem_u32(const void* p) {
    uint32_t a;
    asm("{ .reg .u64 t; cvta.to.shared.u64 t, %1; cvt.u32.u64 %0, t; }" : "=r"(a) : "l"(p));
    return a;
}
__device__ __forceinline__ void ldm_x4(uint32_t* r, uint32_t a) {
    asm volatile("ldmatrix.sync.aligned.m8n8.x4.shared.b16 {%0,%1,%2,%3}, [%4];"
                 : "=r"(r[0]), "=r"(r[1]), "=r"(r[2]), "=r"(r[3]) : "r"(a));
}
__device__ __forceinline__ void ldm_x2(uint32_t* r, uint32_t a) {
    asm volatile("ldmatrix.sync.aligned.m8n8.x2.shared.b16 {%0,%1}, [%2];"
                 : "=r"(r[0]), "=r"(r[1]) : "r"(a));
}
__device__ __forceinline__ void mma_bf16(float* c, const uint32_t* a, const uint32_t* b) {
    asm volatile(
        "mma.sync.aligned.m16n8k16.row.col.f32.bf16.bf16.f32 "
        "{%0,%1,%2,%3}, {%4,%5,%6,%7}, {%8,%9}, {%0,%1,%2,%3};"
        : "+f"(c[0]), "+f"(c[1]), "+f"(c[2]), "+f"(c[3])
        : "r"(a[0]), "r"(a[1]), "r"(a[2]), "r"(a[3]), "r"(b[0]), "r"(b[1]));
}
__device__ __forceinline__ void bf16_split(float v, uint16_t& h, uint16_t& l) {
    __nv_bfloat16 hb = __float2bfloat16(v);
    __nv_bfloat16 lb = __float2bfloat16(v - __bfloat162float(hb));
    h = __bfloat16_as_ushort(hb);
    l = __bfloat16_as_ushort(lb);
}

// ---------------- zero BN accumulators ----------------
__global__ void k_zero() {
    int t = threadIdx.x;
    if (t < CO_) { g_sum[t] = 0.0; g_sumsq[t] = 0.0; }
}

// ---------------- x: NCHW -> NHWC ----------------
__global__ void k_tr_x(const float* __restrict__ x) {
    __shared__ float sm[32][33];
    int b = blockIdx.z, ci0 = blockIdx.y * 32, hw0 = blockIdx.x * 32;
    int tx = threadIdx.x, ty = threadIdx.y;
#pragma unroll
    for (int i = 0; i < 4; ++i) {
        int ci = ci0 + ty + i * 8;
        sm[ty + i * 8][tx] = x[(b * CI_ + ci) * HW_ + hw0 + tx];
    }
    __syncthreads();
#pragma unroll
    for (int i = 0; i < 4; ++i) {
        int hw = hw0 + ty + i * 8;
        g_x_nhwc[(b * HW_ + hw) * CI_ + ci0 + tx] = sm[tx][ty + i * 8];
    }
}

// ---------------- w_dcn -> [tap][co][ci] bf16 hi/lo ----------------
__global__ void k_tr_w2(const float* __restrict__ w_dcn) {
    int idx = blockIdx.x * 256 + threadIdx.x;
    if (idx >= KK_ * CO_ * CI_) return;
    int tap = idx >> 14;
    int r   = idx & 16383;
    int co  = r >> 7;
    int ci  = r & 127;
    float w = w_dcn[(co * CI_ + ci) * KK_ + tap];
    uint16_t h, l;
    bf16_split(w, h, l);
    g_wb_hi[tap * 16384 + co * 128 + ci] = __ushort_as_bfloat16(h);
    g_wb_lo[tap * 16384 + co * 128 + ci] = __ushort_as_bfloat16(l);
}

// ---------------- w_off -> [tap][co32][ci] bf16 hi/lo (pad 18->32) -------------
__global__ void k_tr_wo(const float* __restrict__ w_off) {
    int idx = blockIdx.x * 256 + threadIdx.x;
    if (idx >= KK_ * 32 * CI_) return;
    int tap = idx >> 12;
    int r   = idx & 4095;
    int co  = r >> 7;
    int ci  = r & 127;
    float w = (co < 18) ? w_off[(co * CI_ + ci) * KK_ + tap] : 0.f;
    uint16_t h, l;
    bf16_split(w, h, l);
    g_wo_hi[idx] = __ushort_as_bfloat16(h);
    g_wo_lo[idx] = __ushort_as_bfloat16(l);
}

#define RS 272   // smem row stride (bytes): 17*16B, conflict-free ldmatrix

// ---------------- offset conv, tensorized: 128px x 32co(18), bf16 3-pass -------
#define OFF_AHI 0
#define OFF_ALO 34816
#define OFF_BHI 69632
#define OFF_BLO 78336
#define OFF_TOT 87040

__global__ void __launch_bounds__(256, 2) k_offT(const float* __restrict__ b_off) {
    extern __shared__ char sb[];
    uint32_t sbase = smem_u32(sb);
    int tid = threadIdx.x;
    int wid = tid >> 5, lid = tid & 31;
    int px0 = blockIdx.x * 128;

    float acc[4][4];
#pragma unroll
    for (int ni = 0; ni < 4; ++ni)
#pragma unroll
        for (int j = 0; j < 4; ++j) acc[ni][j] = 0.f;

    uint32_t a_lane = (uint32_t)(wid * 16 + (lid & 15)) * RS + ((lid >> 4) << 4);
    uint32_t b_lane = (uint32_t)(lid & 7) * RS + (((lid >> 3) & 1) << 4);

    for (int k = 0; k < 9; ++k) {
        int ky = k / 3, kx = k - ky * 3;
        __syncthreads();   // prev MMA done
        // B tiles: 32 rows x 256B (hi, lo)
#pragma unroll
        for (int t = 0; t < 2; ++t) {
            int e = tid + t * 256;
            int row = e >> 4, c16 = e & 15;
            *(uint4*)(sb + OFF_BHI + row * RS + c16 * 16) =
                *(const uint4*)(g_wo_hi + k * 4096 + row * 128 + c16 * 8);
            *(uint4*)(sb + OFF_BLO + row * RS + c16 * 16) =
                *(const uint4*)(g_wo_lo + k * 4096 + row * 128 + c16 * 8);
        }
        // A tiles: fixed-tap gather, warp per pixel
#pragma unroll 2
        for (int i = 0; i < 16; ++i) {
            int p = i * 8 + wid;
            int px = px0 + p;
            int b = px >> 14, h = (px >> 7) & 127, w = px & 127;
            int y = h - 1 + ky, xx = w - 1 + kx;
            uint2 hp = make_uint2(0u, 0u), lp = make_uint2(0u, 0u);
            if ((unsigned)y < (unsigned)H_ && (unsigned)xx < (unsigned)W_) {
                float4 v = *(const float4*)(g_x_nhwc + ((b * H_ + y) * W_ + xx) * CI_ + lid * 4);
                uint16_t h0, l0, h1, l1, h2, l2, h3, l3;
                bf16_split(v.x, h0, l0); bf16_split(v.y, h1, l1);
                bf16_split(v.z, h2, l2); bf16_split(v.w, h3, l3);
                hp.x = ((uint32_t)h1 << 16) | h0; hp.y = ((uint32_t)h3 << 16) | h2;
                lp.x = ((uint32_t)l1 << 16) | l0; lp.y = ((uint32_t)l3 << 16) | l2;
            }
            uint32_t off = (uint32_t)p * RS + (uint32_t)lid * 8;
            *(uint2*)(sb + OFF_AHI + off) = hp;
            *(uint2*)(sb + OFF_ALO + off) = lp;
        }
        __syncthreads();
        // MMA
#pragma unroll
        for (int ks = 0; ks < 8; ++ks) {
            uint32_t kb = (uint32_t)ks * 32;
            uint32_t ah[4], al[4];
            ldm_x4(ah, sbase + OFF_AHI + a_lane + kb);
            ldm_x4(al, sbase + OFF_ALO + a_lane + kb);
#pragma unroll
            for (int ni = 0; ni < 4; ++ni) {
                uint32_t ba = b_lane + (uint32_t)(ni * 8) * RS + kb;
                uint32_t bh[2], bl[2];
                ldm_x2(bh, sbase + OFF_BHI + ba);
                ldm_x2(bl, sbase + OFF_BLO + ba);
                mma_bf16(acc[ni], ah, bh);
                mma_bf16(acc[ni], ah, bl);
                mma_bf16(acc[ni], al, bh);
            }
        }
    }
    // epilogue -> g_off [px][18] (+b_off)
    int rofs = lid >> 2, cofs = (lid & 3) * 2;
    int r0 = px0 + wid * 16 + rofs;
#pragma unroll
    for (int ni = 0; ni < 4; ++ni) {
        int c = ni * 8 + cofs;
        if (c < 18) {
            float2 bo = *(const float2*)(b_off + c);
            *(float2*)(g_off + r0 * 18 + c) =
                make_float2(acc[ni][0] + bo.x, acc[ni][1] + bo.y);
            *(float2*)(g_off + (r0 + 8) * 18 + c) =
                make_float2(acc[ni][2] + bo.x, acc[ni][3] + bo.y);
        }
    }
}

// ---------------- main: sampling + HMMA, 64px x 128co, 2 CTA/SM ---------------
#define SM_AHI 0
#define SM_ALO 17408
#define SM_BHI 34816
#define SM_BLO 69632
#define SM_PA  104448
#define SM_PB  105472
#define SM_TOT 106496
#define RSF    132     // stage row stride in floats (33*16B)

__global__ void __launch_bounds__(256, 2) k_mainH2() {
    extern __shared__ char sb[];
    uint32_t sbase = smem_u32(sb);

    int tid = threadIdx.x;
    int wid = tid >> 5, lid = tid & 31;
    int wm = wid >> 2, wn = wid & 3;
    int px0 = blockIdx.x * 64;

    int*   sA = (int*)(sb + SM_PA);
    float* sB = (float*)(sb + SM_PB);

    float acc[2][4][4];
#pragma unroll
    for (int mi = 0; mi < 2; ++mi)
#pragma unroll
        for (int ni = 0; ni < 4; ++ni)
#pragma unroll
            for (int j = 0; j < 4; ++j) acc[mi][ni][j] = 0.f;

    uint32_t a_lane = (uint32_t)(wm * 32 + (lid & 15)) * RS + ((lid >> 4) << 4);
    uint32_t b_lane = (uint32_t)(wn * 32 + (lid & 7)) * RS + (((lid >> 3) & 1) << 4);

    for (int k = 0; k < 9; ++k) {
        __syncthreads();   // prev MMA done before overwriting tiles
        // B tiles (hi/lo): 128 rows x 256B
        {
            int co = tid >> 1, half = tid & 1;
            const uint4* srch = (const uint4*)((const char*)(g_wb_hi + k * 16384 + co * 128) + half * 128);
            const uint4* srcl = (const uint4*)((const char*)(g_wb_lo + k * 16384 + co * 128) + half * 128);
            uint4* dsth = (uint4*)(sb + SM_BHI + co * RS + half * 128);
            uint4* dstl = (uint4*)(sb + SM_BLO + co * RS + half * 128);
#pragma unroll
            for (int t = 0; t < 8; ++t) { dsth[t] = srch[t]; dstl[t] = srcl[t]; }
        }
        // sampling params (64 pixels)
        if (tid < 64) {
            int px = px0 + tid;
            int b = px >> 14, h = (px >> 7) & 127, w = px & 127;
            int ky = k / 3, kx = k - ky * 3;
            float dy = g_off[px * 18 + 2 * k];
            float dx = g_off[px * 18 + 2 * k + 1];
            float ysf = (float)(h - 1 + ky) + dy;
            float xsf = (float)(w - 1 + kx) + dx;
            float fy = floorf(ysf), fx = floorf(xsf);
            float wy = ysf - fy, wx = xsf - fx;
            int iy0 = (int)fy, ix0 = (int)fx;
            int iy1 = iy0 + 1, ix1 = ix0 + 1;
            float my0 = (iy0 >= 0 && iy0 < H_) ? 1.f : 0.f;
            float my1 = (iy1 >= 0 && iy1 < H_) ? 1.f : 0.f;
            float mx0 = (ix0 >= 0 && ix0 < W_) ? 1.f : 0.f;
            float mx1 = (ix1 >= 0 && ix1 < W_) ? 1.f : 0.f;
            int cy0 = min(H_ - 1, max(0, iy0)), cy1 = min(H_ - 1, max(0, iy1));
            int cx0 = min(W_ - 1, max(0, ix0)), cx1 = min(W_ - 1, max(0, ix1));
            int base = b * HW_;
            sA[tid]       = (base + cy0 * W_ + cx0) * CI_;
            sA[64 + tid]  = (base + cy0 * W_ + cx1) * CI_;
            sA[128 + tid] = (base + cy1 * W_ + cx0) * CI_;
            sA[192 + tid] = (base + cy1 * W_ + cx1) * CI_;
            sB[tid]       = (1.f - wy) * (1.f - wx) * my0 * mx0;
            sB[64 + tid]  = (1.f - wy) * wx * my0 * mx1;
            sB[128 + tid] = wy * (1.f - wx) * my1 * mx0;
            sB[192 + tid] = wy * wx * my1 * mx1;
        }
        __syncthreads();

        // sampling: warp per pixel, lane = 4 channels; bf16 hi/lo to A tiles
#pragma unroll 2
        for (int i = 0; i < 8; ++i) {
            int p  = i * 8 + wid;
            int c4 = lid * 4;
            int a00 = sA[p], a01 = sA[64 + p], a10 = sA[128 + p], a11 = sA[192 + p];
            float w00 = sB[p], w01 = sB[64 + p], w10 = sB[128 + p], w11 = sB[192 + p];
            float4 v00 = *(const float4*)(g_x_nhwc + a00 + c4);
            float4 v01 = *(const float4*)(g_x_nhwc + a01 + c4);
            float4 v10 = *(const float4*)(g_x_nhwc + a10 + c4);
            float4 v11 = *(const float4*)(g_x_nhwc + a11 + c4);
            float4 s;
            s.x = fmaf(v11.x, w11, fmaf(v10.x, w10, fmaf(v01.x, w01, v00.x * w00)));
            s.y = fmaf(v11.y, w11, fmaf(v10.y, w10, fmaf(v01.y, w01, v00.y * w00)));
            s.z = fmaf(v11.z, w11, fmaf(v10.z, w10, fmaf(v01.z, w01, v00.z * w00)));
            s.w = fmaf(v11.w, w11, fmaf(v10.w, w10, fmaf(v01.w, w01, v00.w * w00)));
            uint16_t h0, l0, h1, l1, h2, l2, h3, l3;
            bf16_split(s.x, h0, l0); bf16_split(s.y, h1, l1);
            bf16_split(s.z, h2, l2); bf16_split(s.w, h3, l3);
            uint2 hp, lp;
            hp.x = ((uint32_t)h1 << 16) | h0; hp.y = ((uint32_t)h3 << 16) | h2;
            lp.x = ((uint32_t)l1 << 16) | l0; lp.y = ((uint32_t)l3 << 16) | l2;
            uint32_t off = (uint32_t)p * RS + (uint32_t)(c4 * 2);
            *(uint2*)(sb + SM_AHI + off) = hp;
            *(uint2*)(sb + SM_ALO + off) = lp;
        }
        __syncthreads();

        // warp MMA: acc += Ah*Bh + Ah*Bl + Al*Bh
#pragma unroll
        for (int ks = 0; ks < 8; ++ks) {
            uint32_t kb = (uint32_t)ks * 32;
            uint32_t bh[4][2], bl[4][2];
#pragma unroll
            for (int ni = 0; ni < 4; ++ni) {
                uint32_t ba = b_lane + (uint32_t)(ni * 8) * RS + kb;
                ldm_x2(bh[ni], sbase + SM_BHI + ba);
                ldm_x2(bl[ni], sbase + SM_BLO + ba);
            }
#pragma unroll
            for (int mi = 0; mi < 2; ++mi) {
                uint32_t aa = a_lane + (uint32_t)(mi * 16) * RS + kb;
                uint32_t ah[4], al[4];
                ldm_x4(ah, sbase + SM_AHI + aa);
                ldm_x4(al, sbase + SM_ALO + aa);
#pragma unroll
                for (int ni = 0; ni < 4; ++ni) {
                    mma_bf16(acc[mi][ni], ah, bh[ni]);
                    mma_bf16(acc[mi][ni], ah, bl[ni]);
                    mma_bf16(acc[mi][ni], al, bh[ni]);
                }
            }
        }
    }

    // ---- epilogue: stage to smem (conflict-free), coalesced write, BN partials --
    __syncthreads();           // MMA done; A tiles dead -> reuse as stage
    float* stg = (float*)sb;   // [64][RSF]
    int rofs = lid >> 2, cofs = (lid & 3) * 2;
#pragma unroll
    for (int mi = 0; mi < 2; ++mi) {
        int r0 = wm * 32 + mi * 16 + rofs;
#pragma unroll
        for (int ni = 0; ni < 4; ++ni) {
            int co = wn * 32 + ni * 8 + cofs;
            *(float2*)(stg + r0 * RSF + co)       = make_float2(acc[mi][ni][0], acc[mi][ni][1]);
            *(float2*)(stg + (r0 + 8) * RSF + co) = make_float2(acc[mi][ni][2], acc[mi][ni][3]);
        }
    }
    __syncthreads();
    // coalesced store
#pragma unroll
    for (int t = 0; t < 8; ++t) {
        int idx = tid + t * 256;
        int row = idx >> 5, c4 = (idx & 31) * 4;
        float4 v = *(const float4*)(stg + row * RSF + c4);
        *(float4*)(g_out + (px0 + row) * CO_ + c4) = v;
    }
    // BN partials
    {
        int co = tid & 127, half = tid >> 7;
        float s = 0.f, q = 0.f;
#pragma unroll
        for (int r = 0; r < 32; ++r) {
            float v = stg[(half * 32 + r) * RSF + co];
            s += v; q = fmaf(v, v, q);
        }
        float* reds = (float*)(sb + SM_PA);        // 256 floats
        float* redq = reds + 256;                  // 256 floats
        reds[half * 128 + co] = s;
        redq[half * 128 + co] = q;
        __syncthreads();
        if (tid < 128) {
            atomicAdd(&g_sum[tid],   (double)(reds[tid] + reds[128 + tid]));
            atomicAdd(&g_sumsq[tid], (double)(redq[tid] + redq[128 + tid]));
        }
    }
}

// ---------------- BN finalize ----------------
__global__ void k_fin(const float* __restrict__ gamma, const float* __restrict__ beta) {
    int c = threadIdx.x;
    if (c < CO_) {
        double N = (double)NPIX;
        double mean = g_sum[c] / N;
        double var  = g_sumsq[c] / N - mean * mean;
        float a = gamma[c] * rsqrtf((float)var + BN_EPS);
        g_scale[c] = a;
        g_shift[c] = beta[c] - (float)mean * a;
    }
}

// ---------------- apply BN + ReLU + transpose [px][co] -> NCHW ----------------
__global__ void k_apply(float* __restrict__ out) {
    __shared__ float sm[32][33];
    int b = blockIdx.z, co0 = blockIdx.y * 32, hw0 = blockIdx.x * 32;
    int tx = threadIdx.x, ty = threadIdx.y;
#pragma unroll
    for (int i = 0; i < 4; ++i) {
        int hw = hw0 + ty + i * 8;
        sm[ty + i * 8][tx] = g_out[(b * HW_ + hw) * CO_ + co0 + tx];
    }
    __syncthreads();
#pragma unroll
    for (int i = 0; i < 4; ++i) {
        int co = co0 + ty + i * 8;
        float a = g_scale[co], sh = g_shift[co];
        float v = fmaf(sm[tx][ty + i * 8], a, sh);
        out[(b * CO_ + co) * HW_ + hw0 + tx] = fmaxf(v, 0.f);
    }
}

// ---------------- launch ----------------
extern "C" void kernel_launch(void* const* d_in, const int* in_sizes, int n_in,
                              void* d_out, int out_size) {
    const float* x      = (const float*)d_in[0];
    const float* w_off  = (const float*)d_in[1];
    const float* b_off  = (const float*)d_in[2];
    const float* w_dcn  = (const float*)d_in[3];
    const float* gamma  = (const float*)d_in[4];
    const float* beta   = (const float*)d_in[5];
    float* out = (float*)d_out;

    cudaFuncSetAttribute(k_offT,   cudaFuncAttributeMaxDynamicSharedMemorySize, OFF_TOT);
    cudaFuncSetAttribute(k_mainH2, cudaFuncAttributeMaxDynamicSharedMemorySize, SM_TOT);

    dim3 tb(32, 8);
    k_zero<<<1, 128>>>();
    k_tr_x<<<dim3(512, 4, B_), tb>>>(x);
    k_tr_w2<<<576, 256>>>(w_dcn);
    k_tr_wo<<<144, 256>>>(w_off);
    k_offT<<<512, 256, OFF_TOT>>>(b_off);
    k_mainH2<<<1024, 256, SM_TOT>>>();
    k_fin<<<1, 128>>>(gamma, beta);
    k_apply<<<dim3(512, 4, B_), tb>>>(out);
}

// round 5
// speedup vs baseline: 1.7098x; 1.3403x over previous
#include <cuda_runtime.h>
#include <cuda_bf16.h>
#include <cstdint>

#define B_   4
#define CI_  128
#define CO_  128
#define H_   128
#define W_   128
#define HW_  (H_*W_)
#define KK_  9
#define NPIX (B_*HW_)   // 65536
#define BN_EPS 0.001f

// ---------------- scratch ----------------
__device__ float  g_x_nhwc[NPIX*CI_];                          // [b][h][w][ci]
__device__ float  g_off[NPIX*18];                              // [px][18]
__device__ __align__(16) __nv_bfloat16 g_wb_hi[KK_*CO_*CI_];   // [tap][co][ci]
__device__ __align__(16) __nv_bfloat16 g_wb_lo[KK_*CO_*CI_];
__device__ __align__(16) __nv_bfloat16 g_wo_hi[KK_*32*CI_];    // offset conv w
__device__ __align__(16) __nv_bfloat16 g_wo_lo[KK_*32*CI_];
__device__ float  g_out[NPIX*CO_];                             // [px][co]
__device__ double g_sum[CO_];
__device__ double g_sumsq[CO_];
__device__ float  g_scale[CO_];
__device__ float  g_shift[CO_];

__device__ __forceinline__ uint32_t smem_u32(const void* p) {
    uint32_t a;
    asm("{ .reg .u64 t; cvta.to.shared.u64 t, %1; cvt.u32.u64 %0, t; }" : "=r"(a) : "l"(p));
    return a;
}
__device__ __forceinline__ void ldm_x4(uint32_t* r, uint32_t a) {
    asm volatile("ldmatrix.sync.aligned.m8n8.x4.shared.b16 {%0,%1,%2,%3}, [%4];"
                 : "=r"(r[0]), "=r"(r[1]), "=r"(r[2]), "=r"(r[3]) : "r"(a));
}
__device__ __forceinline__ void ldm_x2(uint32_t* r, uint32_t a) {
    asm volatile("ldmatrix.sync.aligned.m8n8.x2.shared.b16 {%0,%1}, [%2];"
                 : "=r"(r[0]), "=r"(r[1]) : "r"(a));
}
__device__ __forceinline__ void mma_bf16(float* c, const uint32_t* a, const uint32_t* b) {
    asm volatile(
        "mma.sync.aligned.m16n8k16.row.col.f32.bf16.bf16.f32 "
        "{%0,%1,%2,%3}, {%4,%5,%6,%7}, {%8,%9}, {%0,%1,%2,%3};"
        : "+f"(c[0]), "+f"(c[1]), "+f"(c[2]), "+f"(c[3])
        : "r"(a[0]), "r"(a[1]), "r"(a[2]), "r"(a[3]), "r"(b[0]), "r"(b[1]));
}
__device__ __forceinline__ void bf16_split(float v, uint16_t& h, uint16_t& l) {
    __nv_bfloat16 hb = __float2bfloat16(v);
    __nv_bfloat16 lb = __float2bfloat16(v - __bfloat162float(hb));
    h = __bfloat16_as_ushort(hb);
    l = __bfloat16_as_ushort(lb);
}
__device__ __forceinline__ void cp16(uint32_t dst, const void* src) {
    asm volatile("cp.async.cg.shared.global [%0], [%1], 16;" :: "r"(dst), "l"(src));
}
__device__ __forceinline__ void cp_commit() { asm volatile("cp.async.commit_group;" ::: "memory"); }
__device__ __forceinline__ void cp_wait0()  { asm volatile("cp.async.wait_group 0;" ::: "memory"); }

// ---------------- zero BN accumulators ----------------
__global__ void k_zero() {
    int t = threadIdx.x;
    if (t < CO_) { g_sum[t] = 0.0; g_sumsq[t] = 0.0; }
}

// ---------------- x: NCHW -> NHWC ----------------
__global__ void k_tr_x(const float* __restrict__ x) {
    __shared__ float sm[32][33];
    int b = blockIdx.z, ci0 = blockIdx.y * 32, hw0 = blockIdx.x * 32;
    int tx = threadIdx.x, ty = threadIdx.y;
#pragma unroll
    for (int i = 0; i < 4; ++i) {
        int ci = ci0 + ty + i * 8;
        sm[ty + i * 8][tx] = x[(b * CI_ + ci) * HW_ + hw0 + tx];
    }
    __syncthreads();
#pragma unroll
    for (int i = 0; i < 4; ++i) {
        int hw = hw0 + ty + i * 8;
        g_x_nhwc[(b * HW_ + hw) * CI_ + ci0 + tx] = sm[tx][ty + i * 8];
    }
}

// ---------------- w_dcn -> [tap][co][ci] bf16 hi/lo ----------------
__global__ void k_tr_w2(const float* __restrict__ w_dcn) {
    int idx = blockIdx.x * 256 + threadIdx.x;
    if (idx >= KK_ * CO_ * CI_) return;
    int tap = idx >> 14;
    int r   = idx & 16383;
    int co  = r >> 7;
    int ci  = r & 127;
    float w = w_dcn[(co * CI_ + ci) * KK_ + tap];
    uint16_t h, l;
    bf16_split(w, h, l);
    g_wb_hi[tap * 16384 + co * 128 + ci] = __ushort_as_bfloat16(h);
    g_wb_lo[tap * 16384 + co * 128 + ci] = __ushort_as_bfloat16(l);
}

// ---------------- w_off -> [tap][co32][ci] bf16 hi/lo (pad 18->32) -------------
__global__ void k_tr_wo(const float* __restrict__ w_off) {
    int idx = blockIdx.x * 256 + threadIdx.x;
    if (idx >= KK_ * 32 * CI_) return;
    int tap = idx >> 12;
    int r   = idx & 4095;
    int co  = r >> 7;
    int ci  = r & 127;
    float w = (co < 18) ? w_off[(co * CI_ + ci) * KK_ + tap] : 0.f;
    uint16_t h, l;
    bf16_split(w, h, l);
    g_wo_hi[idx] = __ushort_as_bfloat16(h);
    g_wo_lo[idx] = __ushort_as_bfloat16(l);
}

#define RS 272   // smem row stride (bytes): 17*16B, conflict-free ldmatrix

// ---------------- offset conv, tensorized: 128px x 32co(18), bf16 3-pass -------
#define OFF_AHI 0
#define OFF_ALO 34816
#define OFF_BHI 69632
#define OFF_BLO 78336
#define OFF_TOT 87040

__global__ void __launch_bounds__(256, 2) k_offT(const float* __restrict__ b_off) {
    extern __shared__ char sb[];
    uint32_t sbase = smem_u32(sb);
    int tid = threadIdx.x;
    int wid = tid >> 5, lid = tid & 31;
    int px0 = blockIdx.x * 128;

    float acc[4][4];
#pragma unroll
    for (int ni = 0; ni < 4; ++ni)
#pragma unroll
        for (int j = 0; j < 4; ++j) acc[ni][j] = 0.f;

    uint32_t a_lane = (uint32_t)(wid * 16 + (lid & 15)) * RS + ((lid >> 4) << 4);
    uint32_t b_lane = (uint32_t)(lid & 7) * RS + (((lid >> 3) & 1) << 4);

    for (int k = 0; k < 9; ++k) {
        int ky = k / 3, kx = k - ky * 3;
        __syncthreads();
#pragma unroll
        for (int t = 0; t < 2; ++t) {
            int e = tid + t * 256;
            int row = e >> 4, c16 = e & 15;
            *(uint4*)(sb + OFF_BHI + row * RS + c16 * 16) =
                *(const uint4*)(g_wo_hi + k * 4096 + row * 128 + c16 * 8);
            *(uint4*)(sb + OFF_BLO + row * RS + c16 * 16) =
                *(const uint4*)(g_wo_lo + k * 4096 + row * 128 + c16 * 8);
        }
#pragma unroll 2
        for (int i = 0; i < 16; ++i) {
            int p = i * 8 + wid;
            int px = px0 + p;
            int b = px >> 14, h = (px >> 7) & 127, w = px & 127;
            int y = h - 1 + ky, xx = w - 1 + kx;
            uint2 hp = make_uint2(0u, 0u), lp = make_uint2(0u, 0u);
            if ((unsigned)y < (unsigned)H_ && (unsigned)xx < (unsigned)W_) {
                float4 v = *(const float4*)(g_x_nhwc + ((b * H_ + y) * W_ + xx) * CI_ + lid * 4);
                uint16_t h0, l0, h1, l1, h2, l2, h3, l3;
                bf16_split(v.x, h0, l0); bf16_split(v.y, h1, l1);
                bf16_split(v.z, h2, l2); bf16_split(v.w, h3, l3);
                hp.x = ((uint32_t)h1 << 16) | h0; hp.y = ((uint32_t)h3 << 16) | h2;
                lp.x = ((uint32_t)l1 << 16) | l0; lp.y = ((uint32_t)l3 << 16) | l2;
            }
            uint32_t off = (uint32_t)p * RS + (uint32_t)lid * 8;
            *(uint2*)(sb + OFF_AHI + off) = hp;
            *(uint2*)(sb + OFF_ALO + off) = lp;
        }
        __syncthreads();
#pragma unroll
        for (int ks = 0; ks < 8; ++ks) {
            uint32_t kb = (uint32_t)ks * 32;
            uint32_t ah[4], al[4];
            ldm_x4(ah, sbase + OFF_AHI + a_lane + kb);
            ldm_x4(al, sbase + OFF_ALO + a_lane + kb);
#pragma unroll
            for (int ni = 0; ni < 4; ++ni) {
                uint32_t ba = b_lane + (uint32_t)(ni * 8) * RS + kb;
                uint32_t bh[2], bl[2];
                ldm_x2(bh, sbase + OFF_BHI + ba);
                ldm_x2(bl, sbase + OFF_BLO + ba);
                mma_bf16(acc[ni], ah, bh);
                mma_bf16(acc[ni], ah, bl);
                mma_bf16(acc[ni], al, bh);
            }
        }
    }
    int rofs = lid >> 2, cofs = (lid & 3) * 2;
    int r0 = px0 + wid * 16 + rofs;
#pragma unroll
    for (int ni = 0; ni < 4; ++ni) {
        int c = ni * 8 + cofs;
        if (c < 18) {
            float2 bo = *(const float2*)(b_off + c);
            *(float2*)(g_off + r0 * 18 + c) =
                make_float2(acc[ni][0] + bo.x, acc[ni][1] + bo.y);
            *(float2*)(g_off + (r0 + 8) * 18 + c) =
                make_float2(acc[ni][2] + bo.x, acc[ni][3] + bo.y);
        }
    }
}

// ---------------- main v3: pipelined sampling + HMMA, 128px x 128co -----------
// 512 thr (16 warps, 4m x 4n, warp tile 32px x 32co), 1 CTA/SM.
// smem: A dbl-buffered (hi+lo per buf), B single (hi+lo), 209 KB.
#define M_ABUF 69632
#define M_LO   34816
#define M_BHI  139264
#define M_BLO  174080
#define M_TOT  208896
#define RSF    132     // epilogue stage row stride (floats)

struct Samp {
    float4 v00, v01, v10, v11;
    float w00, w01, w10, w11;
    uint32_t off;
};

__device__ __forceinline__ void samp_issue(Samp& S, int s, int t, int ky, int kx,
                                           int px0, int wid, int lid) {
    int p = s * 16 + wid;
    int px = px0 + p;
    int b = px >> 14, h = (px >> 7) & 127, w = px & 127;
    float dy = g_off[px * 18 + 2 * t];
    float dx = g_off[px * 18 + 2 * t + 1];
    float ysf = (float)(h - 1 + ky) + dy;
    float xsf = (float)(w - 1 + kx) + dx;
    float fy = floorf(ysf), fx = floorf(xsf);
    float wy = ysf - fy, wx = xsf - fx;
    int iy0 = (int)fy, ix0 = (int)fx;
    int iy1 = iy0 + 1, ix1 = ix0 + 1;
    float my0 = (iy0 >= 0 && iy0 < H_) ? 1.f : 0.f;
    float my1 = (iy1 >= 0 && iy1 < H_) ? 1.f : 0.f;
    float mx0 = (ix0 >= 0 && ix0 < W_) ? 1.f : 0.f;
    float mx1 = (ix1 >= 0 && ix1 < W_) ? 1.f : 0.f;
    int cy0 = min(H_ - 1, max(0, iy0)), cy1 = min(H_ - 1, max(0, iy1));
    int cx0 = min(W_ - 1, max(0, ix0)), cx1 = min(W_ - 1, max(0, ix1));
    int base = b * HW_;
    int c4 = lid * 4;
    S.v00 = *(const float4*)(g_x_nhwc + (base + cy0 * W_ + cx0) * CI_ + c4);
    S.v01 = *(const float4*)(g_x_nhwc + (base + cy0 * W_ + cx1) * CI_ + c4);
    S.v10 = *(const float4*)(g_x_nhwc + (base + cy1 * W_ + cx0) * CI_ + c4);
    S.v11 = *(const float4*)(g_x_nhwc + (base + cy1 * W_ + cx1) * CI_ + c4);
    S.w00 = (1.f - wy) * (1.f - wx) * my0 * mx0;
    S.w01 = (1.f - wy) * wx * my0 * mx1;
    S.w10 = wy * (1.f - wx) * my1 * mx0;
    S.w11 = wy * wx * my1 * mx1;
    S.off = (uint32_t)p * RS + (uint32_t)lid * 8;
}

__device__ __forceinline__ void samp_store(char* sb, uint32_t abase, const Samp& S) {
    float4 s;
    s.x = fmaf(S.v11.x, S.w11, fmaf(S.v10.x, S.w10, fmaf(S.v01.x, S.w01, S.v00.x * S.w00)));
    s.y = fmaf(S.v11.y, S.w11, fmaf(S.v10.y, S.w10, fmaf(S.v01.y, S.w01, S.v00.y * S.w00)));
    s.z = fmaf(S.v11.z, S.w11, fmaf(S.v10.z, S.w10, fmaf(S.v01.z, S.w01, S.v00.z * S.w00)));
    s.w = fmaf(S.v11.w, S.w11, fmaf(S.v10.w, S.w10, fmaf(S.v01.w, S.w01, S.v00.w * S.w00)));
    uint16_t h0, l0, h1, l1, h2, l2, h3, l3;
    bf16_split(s.x, h0, l0); bf16_split(s.y, h1, l1);
    bf16_split(s.z, h2, l2); bf16_split(s.w, h3, l3);
    uint2 hp, lp;
    hp.x = ((uint32_t)h1 << 16) | h0; hp.y = ((uint32_t)h3 << 16) | h2;
    lp.x = ((uint32_t)l1 << 16) | l0; lp.y = ((uint32_t)l3 << 16) | l2;
    *(uint2*)(sb + abase + S.off) = hp;
    *(uint2*)(sb + abase + M_LO + S.off) = lp;
}

__device__ __forceinline__ void copy_B(uint32_t sbase, int k, int tid) {
#pragma unroll
    for (int j = 0; j < 4; ++j) {
        int ch = tid + j * 512;            // 2048 16B chunks per array
        int row = ch >> 4, c16 = ch & 15;
        uint32_t dof = (uint32_t)row * RS + (uint32_t)c16 * 16;
        uint32_t sof = (uint32_t)k * 32768 + (uint32_t)row * 256 + (uint32_t)c16 * 16;
        cp16(sbase + M_BHI + dof, (const char*)g_wb_hi + sof);
        cp16(sbase + M_BLO + dof, (const char*)g_wb_lo + sof);
    }
    cp_commit();
}

__global__ void __launch_bounds__(512, 1) k_main3() {
    extern __shared__ char sb[];
    uint32_t sbase = smem_u32(sb);

    int tid = threadIdx.x;
    int wid = tid >> 5, lid = tid & 31;
    int wm = wid >> 2, wn = wid & 3;
    int px0 = blockIdx.x * 128;

    float acc[2][4][4];
#pragma unroll
    for (int mi = 0; mi < 2; ++mi)
#pragma unroll
        for (int ni = 0; ni < 4; ++ni)
#pragma unroll
            for (int j = 0; j < 4; ++j) acc[mi][ni][j] = 0.f;

    uint32_t a_lane = (uint32_t)(wm * 32 + (lid & 15)) * RS + ((lid >> 4) << 4);
    uint32_t b_lane = (uint32_t)(wn * 32 + (lid & 7)) * RS + (((lid >> 3) & 1) << 4);

    // ---- prologue: B[0] in flight, sample tap 0 into A buf 0 ----
    copy_B(sbase, 0, tid);
    {
        Samp S;
#pragma unroll
        for (int s = 0; s < 8; ++s) {
            samp_issue(S, s, 0, 0, 0, px0, wid, lid);
            samp_store(sb, 0, S);
        }
    }
    cp_wait0();

    for (int k = 0; k < 9; ++k) {
        __syncthreads();                    // A[cur] stores done; MMA(k-1) done -> B free
        if (k >= 1) { copy_B(sbase, k, tid); cp_wait0(); }
        __syncthreads();                    // B[k] visible to all
        uint32_t Acur = (uint32_t)(k & 1) * M_ABUF;
        uint32_t Anxt = (uint32_t)((k & 1) ^ 1) * M_ABUF;
        int t = k + 1;
        int ky = t / 3, kx = t - ky * 3;
        bool samp = (k < 8);
        Samp S[2];
#pragma unroll
        for (int s = 0; s < 8; ++s) {
            if (samp) samp_issue(S[s & 1], s, t, ky, kx, px0, wid, lid);
            // MMA k-step s on A[cur], B
            {
                uint32_t kb = (uint32_t)s * 32;
                uint32_t bh[4][2], bl[4][2];
#pragma unroll
                for (int ni = 0; ni < 4; ++ni) {
                    uint32_t ba = b_lane + (uint32_t)(ni * 8) * RS + kb;
                    ldm_x2(bh[ni], sbase + M_BHI + ba);
                    ldm_x2(bl[ni], sbase + M_BLO + ba);
                }
#pragma unroll
                for (int mi = 0; mi < 2; ++mi) {
                    uint32_t aa = Acur + a_lane + (uint32_t)(mi * 16) * RS + kb;
                    uint32_t ah[4], al[4];
                    ldm_x4(ah, sbase + aa);
                    ldm_x4(al, sbase + aa + M_LO);
#pragma unroll
                    for (int ni = 0; ni < 4; ++ni) {
                        mma_bf16(acc[mi][ni], ah, bh[ni]);
                        mma_bf16(acc[mi][ni], ah, bl[ni]);
                        mma_bf16(acc[mi][ni], al, bh[ni]);
                    }
                }
            }
            if (samp && s > 0) samp_store(sb, Anxt, S[(s - 1) & 1]);
        }
        if (samp) samp_store(sb, Anxt, S[1]);   // slot 7
    }

    // ---- epilogue: stage to smem, coalesced store, BN partials ----
    __syncthreads();
    float* stg = (float*)sb;   // [128][RSF] = 67584 B
    int rofs = lid >> 2, cofs = (lid & 3) * 2;
#pragma unroll
    for (int mi = 0; mi < 2; ++mi) {
        int r0 = wm * 32 + mi * 16 + rofs;
#pragma unroll
        for (int ni = 0; ni < 4; ++ni) {
            int co = wn * 32 + ni * 8 + cofs;
            *(float2*)(stg + r0 * RSF + co)       = make_float2(acc[mi][ni][0], acc[mi][ni][1]);
            *(float2*)(stg + (r0 + 8) * RSF + co) = make_float2(acc[mi][ni][2], acc[mi][ni][3]);
        }
    }
    __syncthreads();
#pragma unroll
    for (int tt = 0; tt < 8; ++tt) {
        int idx = tid + tt * 512;
        int row = idx >> 5, c4 = (idx & 31) * 4;
        float4 v = *(const float4*)(stg + row * RSF + c4);
        *(float4*)(g_out + (px0 + row) * CO_ + c4) = v;
    }
    {
        int co = tid & 127, q = tid >> 7;          // 4 quarters x 32 rows
        float s = 0.f, qq = 0.f;
#pragma unroll
        for (int r = 0; r < 32; ++r) {
            float v = stg[(q * 32 + r) * RSF + co];
            s += v; qq = fmaf(v, v, qq);
        }
        float* reds = (float*)(sb + M_BHI);        // reuse B region
        float* redq = reds + 512;
        reds[q * 128 + co] = s;
        redq[q * 128 + co] = qq;
        __syncthreads();
        if (tid < 128) {
            float ss = reds[tid] + reds[128 + tid] + reds[256 + tid] + reds[384 + tid];
            float sq = redq[tid] + redq[128 + tid] + redq[256 + tid] + redq[384 + tid];
            atomicAdd(&g_sum[tid], (double)ss);
            atomicAdd(&g_sumsq[tid], (double)sq);
        }
    }
}

// ---------------- BN finalize ----------------
__global__ void k_fin(const float* __restrict__ gamma, const float* __restrict__ beta) {
    int c = threadIdx.x;
    if (c < CO_) {
        double N = (double)NPIX;
        double mean = g_sum[c] / N;
        double var  = g_sumsq[c] / N - mean * mean;
        float a = gamma[c] * rsqrtf((float)var + BN_EPS);
        g_scale[c] = a;
        g_shift[c] = beta[c] - (float)mean * a;
    }
}

// ---------------- apply BN + ReLU + transpose [px][co] -> NCHW ----------------
__global__ void k_apply(float* __restrict__ out) {
    __shared__ float sm[32][33];
    int b = blockIdx.z, co0 = blockIdx.y * 32, hw0 = blockIdx.x * 32;
    int tx = threadIdx.x, ty = threadIdx.y;
#pragma unroll
    for (int i = 0; i < 4; ++i) {
        int hw = hw0 + ty + i * 8;
        sm[ty + i * 8][tx] = g_out[(b * HW_ + hw) * CO_ + co0 + tx];
    }
    __syncthreads();
#pragma unroll
    for (int i = 0; i < 4; ++i) {
        int co = co0 + ty + i * 8;
        float a = g_scale[co], sh = g_shift[co];
        float v = fmaf(sm[tx][ty + i * 8], a, sh);
        out[(b * CO_ + co) * HW_ + hw0 + tx] = fmaxf(v, 0.f);
    }
}

// ---------------- launch ----------------
extern "C" void kernel_launch(void* const* d_in, const int* in_sizes, int n_in,
                              void* d_out, int out_size) {
    const float* x      = (const float*)d_in[0];
    const float* w_off  = (const float*)d_in[1];
    const float* b_off  = (const float*)d_in[2];
    const float* w_dcn  = (const float*)d_in[3];
    const float* gamma  = (const float*)d_in[4];
    const float* beta   = (const float*)d_in[5];
    float* out = (float*)d_out;

    cudaFuncSetAttribute(k_offT,  cudaFuncAttributeMaxDynamicSharedMemorySize, OFF_TOT);
    cudaFuncSetAttribute(k_main3, cudaFuncAttributeMaxDynamicSharedMemorySize, M_TOT);

    dim3 tb(32, 8);
    k_zero<<<1, 128>>>();
    k_tr_x<<<dim3(512, 4, B_), tb>>>(x);
    k_tr_w2<<<576, 256>>>(w_dcn);
    k_tr_wo<<<144, 256>>>(w_off);
    k_offT<<<512, 256, OFF_TOT>>>(b_off);
    k_main3<<<512, 512, M_TOT>>>();
    k_fin<<<1, 128>>>(gamma, beta);
    k_apply<<<dim3(512, 4, B_), tb>>>(out);
}

// round 6
// speedup vs baseline: 1.8172x; 1.0628x over previous
#include <cuda_runtime.h>
#include <cuda_bf16.h>
#include <cstdint>

#define B_   4
#define CI_  128
#define CO_  128
#define H_   128
#define W_   128
#define HW_  (H_*W_)
#define KK_  9
#define NPIX (B_*HW_)   // 65536
#define BN_EPS 0.001f

// ---------------- scratch ----------------
__device__ float  g_x_nhwc[NPIX*CI_];                          // [b][h][w][ci]
__device__ float  g_off[NPIX*18];                              // [px][18]
__device__ __align__(16) __nv_bfloat16 g_wb_hi[KK_*CO_*CI_];   // [tap][co][ci]
__device__ __align__(16) __nv_bfloat16 g_wb_lo[KK_*CO_*CI_];
__device__ __align__(16) __nv_bfloat16 g_wo_hi[KK_*32*CI_];    // offset conv w
__device__ __align__(16) __nv_bfloat16 g_wo_lo[KK_*32*CI_];
__device__ float  g_out[NPIX*CO_];                             // [px][co]
__device__ double g_sum[CO_];
__device__ double g_sumsq[CO_];
__device__ float  g_scale[CO_];
__device__ float  g_shift[CO_];

__device__ __forceinline__ uint32_t smem_u32(const void* p) {
    uint32_t a;
    asm("{ .reg .u64 t; cvta.to.shared.u64 t, %1; cvt.u32.u64 %0, t; }" : "=r"(a) : "l"(p));
    return a;
}
__device__ __forceinline__ void ldm_x4(uint32_t* r, uint32_t a) {
    asm volatile("ldmatrix.sync.aligned.m8n8.x4.shared.b16 {%0,%1,%2,%3}, [%4];"
                 : "=r"(r[0]), "=r"(r[1]), "=r"(r[2]), "=r"(r[3]) : "r"(a));
}
__device__ __forceinline__ void ldm_x2(uint32_t* r, uint32_t a) {
    asm volatile("ldmatrix.sync.aligned.m8n8.x2.shared.b16 {%0,%1}, [%2];"
                 : "=r"(r[0]), "=r"(r[1]) : "r"(a));
}
__device__ __forceinline__ void mma_bf16(float* c, const uint32_t* a, const uint32_t* b) {
    asm volatile(
        "mma.sync.aligned.m16n8k16.row.col.f32.bf16.bf16.f32 "
        "{%0,%1,%2,%3}, {%4,%5,%6,%7}, {%8,%9}, {%0,%1,%2,%3};"
        : "+f"(c[0]), "+f"(c[1]), "+f"(c[2]), "+f"(c[3])
        : "r"(a[0]), "r"(a[1]), "r"(a[2]), "r"(a[3]), "r"(b[0]), "r"(b[1]));
}
__device__ __forceinline__ void bf16_split(float v, uint16_t& h, uint16_t& l) {
    __nv_bfloat16 hb = __float2bfloat16(v);
    __nv_bfloat16 lb = __float2bfloat16(v - __bfloat162float(hb));
    h = __bfloat16_as_ushort(hb);
    l = __bfloat16_as_ushort(lb);
}
// pack high-16 of two floats into one bf16x2 (truncation)
__device__ __forceinline__ uint32_t prmt_hi(uint32_t a, uint32_t b) {
    uint32_t d;
    asm("prmt.b32 %0, %1, %2, 0x7632;" : "=r"(d) : "r"(a), "r"(b));
    return d;
}
// truncation hi/lo split of float4 -> bf16x2 pairs
__device__ __forceinline__ void split4(float4 s, uint2& hp, uint2& lp) {
    uint32_t u0 = __float_as_uint(s.x), u1 = __float_as_uint(s.y);
    uint32_t u2 = __float_as_uint(s.z), u3 = __float_as_uint(s.w);
    hp.x = prmt_hi(u0, u1);
    hp.y = prmt_hi(u2, u3);
    float l0 = s.x - __uint_as_float(u0 & 0xFFFF0000u);
    float l1 = s.y - __uint_as_float(u1 & 0xFFFF0000u);
    float l2 = s.z - __uint_as_float(u2 & 0xFFFF0000u);
    float l3 = s.w - __uint_as_float(u3 & 0xFFFF0000u);
    lp.x = prmt_hi(__float_as_uint(l0), __float_as_uint(l1));
    lp.y = prmt_hi(__float_as_uint(l2), __float_as_uint(l3));
}
__device__ __forceinline__ void cp16(uint32_t dst, const void* src) {
    asm volatile("cp.async.cg.shared.global [%0], [%1], 16;" :: "r"(dst), "l"(src));
}
__device__ __forceinline__ void cp_commit() { asm volatile("cp.async.commit_group;" ::: "memory"); }
__device__ __forceinline__ void cp_wait0()  { asm volatile("cp.async.wait_group 0;" ::: "memory"); }

// ---------------- x: NCHW -> NHWC ----------------
__global__ void k_tr_x(const float* __restrict__ x) {
    __shared__ float sm[32][33];
    int b = blockIdx.z, ci0 = blockIdx.y * 32, hw0 = blockIdx.x * 32;
    int tx = threadIdx.x, ty = threadIdx.y;
#pragma unroll
    for (int i = 0; i < 4; ++i) {
        int ci = ci0 + ty + i * 8;
        sm[ty + i * 8][tx] = x[(b * CI_ + ci) * HW_ + hw0 + tx];
    }
    __syncthreads();
#pragma unroll
    for (int i = 0; i < 4; ++i) {
        int hw = hw0 + ty + i * 8;
        g_x_nhwc[(b * HW_ + hw) * CI_ + ci0 + tx] = sm[tx][ty + i * 8];
    }
}

// ---------------- prep: BN zero + both weight transforms (merged) -------------
__global__ void k_prep(const float* __restrict__ w_dcn, const float* __restrict__ w_off) {
    int idx = blockIdx.x * 256 + threadIdx.x;
    if (idx < 128) { g_sum[idx] = 0.0; g_sumsq[idx] = 0.0; }
    if (idx < KK_ * CO_ * CI_) {
        int tap = idx >> 14;
        int r   = idx & 16383;
        int co  = r >> 7;
        int ci  = r & 127;
        float w = w_dcn[(co * CI_ + ci) * KK_ + tap];
        uint16_t h, l;
        bf16_split(w, h, l);
        g_wb_hi[idx] = __ushort_as_bfloat16(h);
        g_wb_lo[idx] = __ushort_as_bfloat16(l);
    }
    if (idx < KK_ * 32 * CI_) {
        int tap = idx >> 12;
        int r   = idx & 4095;
        int co  = r >> 7;
        int ci  = r & 127;
        float w = (co < 18) ? w_off[(co * CI_ + ci) * KK_ + tap] : 0.f;
        uint16_t h, l;
        bf16_split(w, h, l);
        g_wo_hi[idx] = __ushort_as_bfloat16(h);
        g_wo_lo[idx] = __ushort_as_bfloat16(l);
    }
}

#define RS 272   // smem row stride (bytes): 17*16B, conflict-free ldmatrix

// ---------------- offset conv, tensorized: 128px x 32co(18), bf16 3-pass -------
#define OFF_AHI 0
#define OFF_ALO 34816
#define OFF_BHI 69632
#define OFF_BLO 78336
#define OFF_TOT 87040

__global__ void __launch_bounds__(256, 2) k_offT(const float* __restrict__ b_off) {
    extern __shared__ char sb[];
    uint32_t sbase = smem_u32(sb);
    int tid = threadIdx.x;
    int wid = tid >> 5, lid = tid & 31;
    int px0 = blockIdx.x * 128;

    float acc[4][4];
#pragma unroll
    for (int ni = 0; ni < 4; ++ni)
#pragma unroll
        for (int j = 0; j < 4; ++j) acc[ni][j] = 0.f;

    uint32_t a_lane = (uint32_t)(wid * 16 + (lid & 15)) * RS + ((lid >> 4) << 4);
    // x4 B-lane: covers 16 n-rows per load
    uint32_t b_lane4 = (uint32_t)((lid & 7) | ((lid >> 4) << 3)) * RS + (((lid >> 3) & 1) << 4);

    for (int k = 0; k < 9; ++k) {
        int ky = k / 3, kx = k - ky * 3;
        __syncthreads();
#pragma unroll
        for (int t = 0; t < 2; ++t) {
            int e = tid + t * 256;
            int row = e >> 4, c16 = e & 15;
            *(uint4*)(sb + OFF_BHI + row * RS + c16 * 16) =
                *(const uint4*)(g_wo_hi + k * 4096 + row * 128 + c16 * 8);
            *(uint4*)(sb + OFF_BLO + row * RS + c16 * 16) =
                *(const uint4*)(g_wo_lo + k * 4096 + row * 128 + c16 * 8);
        }
#pragma unroll 2
        for (int i = 0; i < 16; ++i) {
            int p = i * 8 + wid;
            int px = px0 + p;
            int b = px >> 14, h = (px >> 7) & 127, w = px & 127;
            int y = h - 1 + ky, xx = w - 1 + kx;
            uint2 hp = make_uint2(0u, 0u), lp = make_uint2(0u, 0u);
            if ((unsigned)y < (unsigned)H_ && (unsigned)xx < (unsigned)W_) {
                float4 v = *(const float4*)(g_x_nhwc + ((b * H_ + y) * W_ + xx) * CI_ + lid * 4);
                split4(v, hp, lp);
            }
            uint32_t off = (uint32_t)p * RS + (uint32_t)lid * 8;
            *(uint2*)(sb + OFF_AHI + off) = hp;
            *(uint2*)(sb + OFF_ALO + off) = lp;
        }
        __syncthreads();
#pragma unroll
        for (int ks = 0; ks < 8; ++ks) {
            uint32_t kb = (uint32_t)ks * 32;
            uint32_t ah[4], al[4];
            ldm_x4(ah, sbase + OFF_AHI + a_lane + kb);
            ldm_x4(al, sbase + OFF_ALO + a_lane + kb);
#pragma unroll
            for (int ni2 = 0; ni2 < 2; ++ni2) {
                uint32_t ba = b_lane4 + (uint32_t)(ni2 * 16) * RS + kb;
                uint32_t bh4[4], bl4[4];
                ldm_x4(bh4, sbase + OFF_BHI + ba);
                ldm_x4(bl4, sbase + OFF_BLO + ba);
                mma_bf16(acc[ni2 * 2 + 0], ah, bh4);
                mma_bf16(acc[ni2 * 2 + 0], ah, bl4);
                mma_bf16(acc[ni2 * 2 + 0], al, bh4);
                mma_bf16(acc[ni2 * 2 + 1], ah, bh4 + 2);
                mma_bf16(acc[ni2 * 2 + 1], ah, bl4 + 2);
                mma_bf16(acc[ni2 * 2 + 1], al, bh4 + 2);
            }
        }
    }
    int rofs = lid >> 2, cofs = (lid & 3) * 2;
    int r0 = px0 + wid * 16 + rofs;
#pragma unroll
    for (int ni = 0; ni < 4; ++ni) {
        int c = ni * 8 + cofs;
        if (c < 18) {
            float2 bo = *(const float2*)(b_off + c);
            *(float2*)(g_off + r0 * 18 + c) =
                make_float2(acc[ni][0] + bo.x, acc[ni][1] + bo.y);
            *(float2*)(g_off + (r0 + 8) * 18 + c) =
                make_float2(acc[ni][2] + bo.x, acc[ni][3] + bo.y);
        }
    }
}

// ---------------- main v3: pipelined sampling + HMMA, 128px x 128co -----------
#define M_ABUF 69632
#define M_LO   34816
#define M_BHI  139264
#define M_BLO  174080
#define M_TOT  208896
#define RSF    132

struct Samp {
    float4 v00, v01, v10, v11;
    float w00, w01, w10, w11;
    uint32_t off;
};

__device__ __forceinline__ void samp_issue(Samp& S, int s, int t, int ky, int kx,
                                           int px0, int wid, int lid) {
    int p = s * 16 + wid;
    int px = px0 + p;
    int b = px >> 14, h = (px >> 7) & 127, w = px & 127;
    float dy = g_off[px * 18 + 2 * t];
    float dx = g_off[px * 18 + 2 * t + 1];
    float ysf = (float)(h - 1 + ky) + dy;
    float xsf = (float)(w - 1 + kx) + dx;
    float fy = floorf(ysf), fx = floorf(xsf);
    float wy = ysf - fy, wx = xsf - fx;
    int iy0 = (int)fy, ix0 = (int)fx;
    int iy1 = iy0 + 1, ix1 = ix0 + 1;
    float my0 = (iy0 >= 0 && iy0 < H_) ? 1.f : 0.f;
    float my1 = (iy1 >= 0 && iy1 < H_) ? 1.f : 0.f;
    float mx0 = (ix0 >= 0 && ix0 < W_) ? 1.f : 0.f;
    float mx1 = (ix1 >= 0 && ix1 < W_) ? 1.f : 0.f;
    int cy0 = min(H_ - 1, max(0, iy0)), cy1 = min(H_ - 1, max(0, iy1));
    int cx0 = min(W_ - 1, max(0, ix0)), cx1 = min(W_ - 1, max(0, ix1));
    int base = b * HW_;
    int c4 = lid * 4;
    S.v00 = *(const float4*)(g_x_nhwc + (base + cy0 * W_ + cx0) * CI_ + c4);
    S.v01 = *(const float4*)(g_x_nhwc + (base + cy0 * W_ + cx1) * CI_ + c4);
    S.v10 = *(const float4*)(g_x_nhwc + (base + cy1 * W_ + cx0) * CI_ + c4);
    S.v11 = *(const float4*)(g_x_nhwc + (base + cy1 * W_ + cx1) * CI_ + c4);
    S.w00 = (1.f - wy) * (1.f - wx) * my0 * mx0;
    S.w01 = (1.f - wy) * wx * my0 * mx1;
    S.w10 = wy * (1.f - wx) * my1 * mx0;
    S.w11 = wy * wx * my1 * mx1;
    S.off = (uint32_t)p * RS + (uint32_t)lid * 8;
}

__device__ __forceinline__ void samp_store(char* sb, uint32_t abase, const Samp& S) {
    float4 s;
    s.x = fmaf(S.v11.x, S.w11, fmaf(S.v10.x, S.w10, fmaf(S.v01.x, S.w01, S.v00.x * S.w00)));
    s.y = fmaf(S.v11.y, S.w11, fmaf(S.v10.y, S.w10, fmaf(S.v01.y, S.w01, S.v00.y * S.w00)));
    s.z = fmaf(S.v11.z, S.w11, fmaf(S.v10.z, S.w10, fmaf(S.v01.z, S.w01, S.v00.z * S.w00)));
    s.w = fmaf(S.v11.w, S.w11, fmaf(S.v10.w, S.w10, fmaf(S.v01.w, S.w01, S.v00.w * S.w00)));
    uint2 hp, lp;
    split4(s, hp, lp);
    *(uint2*)(sb + abase + S.off) = hp;
    *(uint2*)(sb + abase + M_LO + S.off) = lp;
}

__device__ __forceinline__ void copy_B(uint32_t sbase, int k, int tid) {
#pragma unroll
    for (int j = 0; j < 4; ++j) {
        int ch = tid + j * 512;
        int row = ch >> 4, c16 = ch & 15;
        uint32_t dof = (uint32_t)row * RS + (uint32_t)c16 * 16;
        uint32_t sof = (uint32_t)k * 32768 + (uint32_t)row * 256 + (uint32_t)c16 * 16;
        cp16(sbase + M_BHI + dof, (const char*)g_wb_hi + sof);
        cp16(sbase + M_BLO + dof, (const char*)g_wb_lo + sof);
    }
    cp_commit();
}

__global__ void __launch_bounds__(512, 1) k_main3() {
    extern __shared__ char sb[];
    uint32_t sbase = smem_u32(sb);

    int tid = threadIdx.x;
    int wid = tid >> 5, lid = tid & 31;
    int wm = wid >> 2, wn = wid & 3;
    int px0 = blockIdx.x * 128;

    float acc[2][4][4];
#pragma unroll
    for (int mi = 0; mi < 2; ++mi)
#pragma unroll
        for (int ni = 0; ni < 4; ++ni)
#pragma unroll
            for (int j = 0; j < 4; ++j) acc[mi][ni][j] = 0.f;

    uint32_t a_lane = (uint32_t)(wm * 32 + (lid & 15)) * RS + ((lid >> 4) << 4);
    uint32_t b_lane4 = (uint32_t)(wn * 32 + ((lid & 7) | ((lid >> 4) << 3))) * RS
                     + (((lid >> 3) & 1) << 4);

    // prologue: B[0] in flight, sample tap 0 into A buf 0
    copy_B(sbase, 0, tid);
    {
        Samp S;
#pragma unroll
        for (int s = 0; s < 8; ++s) {
            samp_issue(S, s, 0, 0, 0, px0, wid, lid);
            samp_store(sb, 0, S);
        }
    }
    cp_wait0();

    for (int k = 0; k < 9; ++k) {
        __syncthreads();
        if (k >= 1) { copy_B(sbase, k, tid); cp_wait0(); }
        __syncthreads();
        uint32_t Acur = (uint32_t)(k & 1) * M_ABUF;
        uint32_t Anxt = (uint32_t)((k & 1) ^ 1) * M_ABUF;
        int t = k + 1;
        int ky = t / 3, kx = t - ky * 3;
        bool samp = (k < 8);
        Samp S[2];
#pragma unroll
        for (int s = 0; s < 8; ++s) {
            if (samp) samp_issue(S[s & 1], s, t, ky, kx, px0, wid, lid);
            {
                uint32_t kb = (uint32_t)s * 32;
                uint32_t bh4[2][4], bl4[2][4];
#pragma unroll
                for (int ni2 = 0; ni2 < 2; ++ni2) {
                    uint32_t ba = b_lane4 + (uint32_t)(ni2 * 16) * RS + kb;
                    ldm_x4(bh4[ni2], sbase + M_BHI + ba);
                    ldm_x4(bl4[ni2], sbase + M_BLO + ba);
                }
#pragma unroll
                for (int mi = 0; mi < 2; ++mi) {
                    uint32_t aa = Acur + a_lane + (uint32_t)(mi * 16) * RS + kb;
                    uint32_t ah[4], al[4];
                    ldm_x4(ah, sbase + aa);
                    ldm_x4(al, sbase + aa + M_LO);
#pragma unroll
                    for (int ni2 = 0; ni2 < 2; ++ni2) {
#pragma unroll
                        for (int half = 0; half < 2; ++half) {
                            float* c = acc[mi][ni2 * 2 + half];
                            mma_bf16(c, ah, bh4[ni2] + half * 2);
                            mma_bf16(c, ah, bl4[ni2] + half * 2);
                            mma_bf16(c, al, bh4[ni2] + half * 2);
                        }
                    }
                }
            }
            if (samp && s > 0) samp_store(sb, Anxt, S[(s - 1) & 1]);
        }
        if (samp) samp_store(sb, Anxt, S[1]);
    }

    // epilogue: stage to smem, coalesced store, BN partials
    __syncthreads();
    float* stg = (float*)sb;
    int rofs = lid >> 2, cofs = (lid & 3) * 2;
#pragma unroll
    for (int mi = 0; mi < 2; ++mi) {
        int r0 = wm * 32 + mi * 16 + rofs;
#pragma unroll
        for (int ni = 0; ni < 4; ++ni) {
            int co = wn * 32 + ni * 8 + cofs;
            *(float2*)(stg + r0 * RSF + co)       = make_float2(acc[mi][ni][0], acc[mi][ni][1]);
            *(float2*)(stg + (r0 + 8) * RSF + co) = make_float2(acc[mi][ni][2], acc[mi][ni][3]);
        }
    }
    __syncthreads();
#pragma unroll
    for (int tt = 0; tt < 8; ++tt) {
        int idx = tid + tt * 512;
        int row = idx >> 5, c4 = (idx & 31) * 4;
        float4 v = *(const float4*)(stg + row * RSF + c4);
        *(float4*)(g_out + (px0 + row) * CO_ + c4) = v;
    }
    {
        int co = tid & 127, q = tid >> 7;
        float s = 0.f, qq = 0.f;
#pragma unroll
        for (int r = 0; r < 32; ++r) {
            float v = stg[(q * 32 + r) * RSF + co];
            s += v; qq = fmaf(v, v, qq);
        }
        float* reds = (float*)(sb + M_BHI);
        float* redq = reds + 512;
        reds[q * 128 + co] = s;
        redq[q * 128 + co] = qq;
        __syncthreads();
        if (tid < 128) {
            float ss = reds[tid] + reds[128 + tid] + reds[256 + tid] + reds[384 + tid];
            float sq = redq[tid] + redq[128 + tid] + redq[256 + tid] + redq[384 + tid];
            atomicAdd(&g_sum[tid], (double)ss);
            atomicAdd(&g_sumsq[tid], (double)sq);
        }
    }
}

// ---------------- BN finalize ----------------
__global__ void k_fin(const float* __restrict__ gamma, const float* __restrict__ beta) {
    int c = threadIdx.x;
    if (c < CO_) {
        double N = (double)NPIX;
        double mean = g_sum[c] / N;
        double var  = g_sumsq[c] / N - mean * mean;
        float a = gamma[c] * rsqrtf((float)var + BN_EPS);
        g_scale[c] = a;
        g_shift[c] = beta[c] - (float)mean * a;
    }
}

// ---------------- apply BN + ReLU + transpose [px][co] -> NCHW ----------------
__global__ void k_apply(float* __restrict__ out) {
    __shared__ float sm[32][33];
    int b = blockIdx.z, co0 = blockIdx.y * 32, hw0 = blockIdx.x * 32;
    int tx = threadIdx.x, ty = threadIdx.y;
#pragma unroll
    for (int i = 0; i < 4; ++i) {
        int hw = hw0 + ty + i * 8;
        sm[ty + i * 8][tx] = g_out[(b * HW_ + hw) * CO_ + co0 + tx];
    }
    __syncthreads();
#pragma unroll
    for (int i = 0; i < 4; ++i) {
        int co = co0 + ty + i * 8;
        float a = g_scale[co], sh = g_shift[co];
        float v = fmaf(sm[tx][ty + i * 8], a, sh);
        out[(b * CO_ + co) * HW_ + hw0 + tx] = fmaxf(v, 0.f);
    }
}

// ---------------- launch ----------------
extern "C" void kernel_launch(void* const* d_in, const int* in_sizes, int n_in,
                              void* d_out, int out_size) {
    const float* x      = (const float*)d_in[0];
    const float* w_off  = (const float*)d_in[1];
    const float* b_off  = (const float*)d_in[2];
    const float* w_dcn  = (const float*)d_in[3];
    const float* gamma  = (const float*)d_in[4];
    const float* beta   = (const float*)d_in[5];
    float* out = (float*)d_out;

    cudaFuncSetAttribute(k_offT,  cudaFuncAttributeMaxDynamicSharedMemorySize, OFF_TOT);
    cudaFuncSetAttribute(k_main3, cudaFuncAttributeMaxDynamicSharedMemorySize, M_TOT);

    dim3 tb(32, 8);
    k_tr_x<<<dim3(512, 4, B_), tb>>>(x);          // launch 0
    k_prep<<<576, 256>>>(w_dcn, w_off);           // launch 1 (zero + both w transforms)
    k_offT<<<512, 256, OFF_TOT>>>(b_off);         // launch 2
    k_main3<<<512, 512, M_TOT>>>();               // launch 3  <- ncu capture slot
    k_fin<<<1, 128>>>(gamma, beta);               // launch 4
    k_apply<<<dim3(512, 4, B_), tb>>>(out);       // launch 5
}

// round 7
// speedup vs baseline: 1.8654x; 1.0265x over previous
#include <cuda_runtime.h>
#include <cuda_bf16.h>
#include <cstdint>

#define B_   4
#define CI_  128
#define CO_  128
#define H_   128
#define W_   128
#define HW_  (H_*W_)
#define KK_  9
#define NPIX (B_*HW_)   // 65536
#define BN_EPS 0.001f

// ---------------- scratch ----------------
__device__ float  g_x_nhwc[NPIX*CI_];                          // [b][h][w][ci]
__device__ float  g_off[NPIX*18];                              // [px][18]
__device__ __align__(16) __nv_bfloat16 g_wb_hi[KK_*CO_*CI_];   // [tap][co][ci]
__device__ __align__(16) __nv_bfloat16 g_wb_lo[KK_*CO_*CI_];
__device__ __align__(16) __nv_bfloat16 g_wo_hi[KK_*32*CI_];    // offset conv w
__device__ __align__(16) __nv_bfloat16 g_wo_lo[KK_*32*CI_];
__device__ float  g_out[NPIX*CO_];                             // [px][co]
__device__ double g_sum[CO_];
__device__ double g_sumsq[CO_];
__device__ float  g_scale[CO_];
__device__ float  g_shift[CO_];

__device__ __forceinline__ uint32_t smem_u32(const void* p) {
    uint32_t a;
    asm("{ .reg .u64 t; cvta.to.shared.u64 t, %1; cvt.u32.u64 %0, t; }" : "=r"(a) : "l"(p));
    return a;
}
__device__ __forceinline__ void ldm_x4(uint32_t* r, uint32_t a) {
    asm volatile("ldmatrix.sync.aligned.m8n8.x4.shared.b16 {%0,%1,%2,%3}, [%4];"
                 : "=r"(r[0]), "=r"(r[1]), "=r"(r[2]), "=r"(r[3]) : "r"(a));
}
__device__ __forceinline__ void mma_bf16(float* c, const uint32_t* a, const uint32_t* b) {
    asm volatile(
        "mma.sync.aligned.m16n8k16.row.col.f32.bf16.bf16.f32 "
        "{%0,%1,%2,%3}, {%4,%5,%6,%7}, {%8,%9}, {%0,%1,%2,%3};"
        : "+f"(c[0]), "+f"(c[1]), "+f"(c[2]), "+f"(c[3])
        : "r"(a[0]), "r"(a[1]), "r"(a[2]), "r"(a[3]), "r"(b[0]), "r"(b[1]));
}
__device__ __forceinline__ void bf16_split(float v, uint16_t& h, uint16_t& l) {
    __nv_bfloat16 hb = __float2bfloat16(v);
    __nv_bfloat16 lb = __float2bfloat16(v - __bfloat162float(hb));
    h = __bfloat16_as_ushort(hb);
    l = __bfloat16_as_ushort(lb);
}
__device__ __forceinline__ uint32_t prmt_hi(uint32_t a, uint32_t b) {
    uint32_t d;
    asm("prmt.b32 %0, %1, %2, 0x7632;" : "=r"(d) : "r"(a), "r"(b));
    return d;
}
__device__ __forceinline__ void split4(float4 s, uint2& hp, uint2& lp) {
    uint32_t u0 = __float_as_uint(s.x), u1 = __float_as_uint(s.y);
    uint32_t u2 = __float_as_uint(s.z), u3 = __float_as_uint(s.w);
    hp.x = prmt_hi(u0, u1);
    hp.y = prmt_hi(u2, u3);
    float l0 = s.x - __uint_as_float(u0 & 0xFFFF0000u);
    float l1 = s.y - __uint_as_float(u1 & 0xFFFF0000u);
    float l2 = s.z - __uint_as_float(u2 & 0xFFFF0000u);
    float l3 = s.w - __uint_as_float(u3 & 0xFFFF0000u);
    lp.x = prmt_hi(__float_as_uint(l0), __float_as_uint(l1));
    lp.y = prmt_hi(__float_as_uint(l2), __float_as_uint(l3));
}
__device__ __forceinline__ void cp16(uint32_t dst, const void* src) {
    asm volatile("cp.async.cg.shared.global [%0], [%1], 16;" :: "r"(dst), "l"(src));
}
__device__ __forceinline__ void cp_commit() { asm volatile("cp.async.commit_group;" ::: "memory"); }
__device__ __forceinline__ void cp_wait0()  { asm volatile("cp.async.wait_group 0;" ::: "memory"); }

// ---------------- x: NCHW -> NHWC ----------------
__global__ void k_tr_x(const float* __restrict__ x) {
    __shared__ float sm[32][33];
    int b = blockIdx.z, ci0 = blockIdx.y * 32, hw0 = blockIdx.x * 32;
    int tx = threadIdx.x, ty = threadIdx.y;
#pragma unroll
    for (int i = 0; i < 4; ++i) {
        int ci = ci0 + ty + i * 8;
        sm[ty + i * 8][tx] = x[(b * CI_ + ci) * HW_ + hw0 + tx];
    }
    __syncthreads();
#pragma unroll
    for (int i = 0; i < 4; ++i) {
        int hw = hw0 + ty + i * 8;
        g_x_nhwc[(b * HW_ + hw) * CI_ + ci0 + tx] = sm[tx][ty + i * 8];
    }
}

// ---------------- prep: BN zero + both weight transforms ----------------
__global__ void k_prep(const float* __restrict__ w_dcn, const float* __restrict__ w_off) {
    int idx = blockIdx.x * 256 + threadIdx.x;
    if (idx < 128) { g_sum[idx] = 0.0; g_sumsq[idx] = 0.0; }
    if (idx < KK_ * CO_ * CI_) {
        int tap = idx >> 14;
        int r   = idx & 16383;
        int co  = r >> 7;
        int ci  = r & 127;
        float w = w_dcn[(co * CI_ + ci) * KK_ + tap];
        uint16_t h, l;
        bf16_split(w, h, l);
        g_wb_hi[idx] = __ushort_as_bfloat16(h);
        g_wb_lo[idx] = __ushort_as_bfloat16(l);
    }
    if (idx < KK_ * 32 * CI_) {
        int tap = idx >> 12;
        int r   = idx & 4095;
        int co  = r >> 7;
        int ci  = r & 127;
        float w = (co < 18) ? w_off[(co * CI_ + ci) * KK_ + tap] : 0.f;
        uint16_t h, l;
        bf16_split(w, h, l);
        g_wo_hi[idx] = __ushort_as_bfloat16(h);
        g_wo_lo[idx] = __ushort_as_bfloat16(l);
    }
}

#define RS 272   // smem row stride (bytes): 17*16B, conflict-free ldmatrix

// ---------------- offset conv, tensorized ----------------
#define OFF_AHI 0
#define OFF_ALO 34816
#define OFF_BHI 69632
#define OFF_BLO 78336
#define OFF_TOT 87040

__global__ void __launch_bounds__(256, 2) k_offT(const float* __restrict__ b_off) {
    extern __shared__ char sb[];
    uint32_t sbase = smem_u32(sb);
    int tid = threadIdx.x;
    int wid = tid >> 5, lid = tid & 31;
    int px0 = blockIdx.x * 128;

    float acc[4][4];
#pragma unroll
    for (int ni = 0; ni < 4; ++ni)
#pragma unroll
        for (int j = 0; j < 4; ++j) acc[ni][j] = 0.f;

    uint32_t a_lane = (uint32_t)(wid * 16 + (lid & 15)) * RS + ((lid >> 4) << 4);
    uint32_t b_lane4 = (uint32_t)((lid & 7) | ((lid >> 4) << 3)) * RS + (((lid >> 3) & 1) << 4);

    for (int k = 0; k < 9; ++k) {
        int ky = k / 3, kx = k - ky * 3;
        __syncthreads();
#pragma unroll
        for (int t = 0; t < 2; ++t) {
            int e = tid + t * 256;
            int row = e >> 4, c16 = e & 15;
            *(uint4*)(sb + OFF_BHI + row * RS + c16 * 16) =
                *(const uint4*)(g_wo_hi + k * 4096 + row * 128 + c16 * 8);
            *(uint4*)(sb + OFF_BLO + row * RS + c16 * 16) =
                *(const uint4*)(g_wo_lo + k * 4096 + row * 128 + c16 * 8);
        }
#pragma unroll 2
        for (int i = 0; i < 16; ++i) {
            int p = i * 8 + wid;
            int px = px0 + p;
            int b = px >> 14, h = (px >> 7) & 127, w = px & 127;
            int y = h - 1 + ky, xx = w - 1 + kx;
            uint2 hp = make_uint2(0u, 0u), lp = make_uint2(0u, 0u);
            if ((unsigned)y < (unsigned)H_ && (unsigned)xx < (unsigned)W_) {
                float4 v = *(const float4*)(g_x_nhwc + ((b * H_ + y) * W_ + xx) * CI_ + lid * 4);
                split4(v, hp, lp);
            }
            uint32_t off = (uint32_t)p * RS + (uint32_t)lid * 8;
            *(uint2*)(sb + OFF_AHI + off) = hp;
            *(uint2*)(sb + OFF_ALO + off) = lp;
        }
        __syncthreads();
#pragma unroll
        for (int ks = 0; ks < 8; ++ks) {
            uint32_t kb = (uint32_t)ks * 32;
            uint32_t ah[4], al[4], bh4[2][4], bl4[2][4];
            ldm_x4(ah, sbase + OFF_AHI + a_lane + kb);
            ldm_x4(al, sbase + OFF_ALO + a_lane + kb);
#pragma unroll
            for (int ni2 = 0; ni2 < 2; ++ni2) {
                uint32_t ba = b_lane4 + (uint32_t)(ni2 * 16) * RS + kb;
                ldm_x4(bh4[ni2], sbase + OFF_BHI + ba);
                ldm_x4(bl4[ni2], sbase + OFF_BLO + ba);
            }
            // pass-major: all hh, then hl, then lh (max acc-reuse distance)
#pragma unroll
            for (int ni2 = 0; ni2 < 2; ++ni2)
#pragma unroll
                for (int half = 0; half < 2; ++half)
                    mma_bf16(acc[ni2 * 2 + half], ah, bh4[ni2] + half * 2);
#pragma unroll
            for (int ni2 = 0; ni2 < 2; ++ni2)
#pragma unroll
                for (int half = 0; half < 2; ++half)
                    mma_bf16(acc[ni2 * 2 + half], ah, bl4[ni2] + half * 2);
#pragma unroll
            for (int ni2 = 0; ni2 < 2; ++ni2)
#pragma unroll
                for (int half = 0; half < 2; ++half)
                    mma_bf16(acc[ni2 * 2 + half], al, bh4[ni2] + half * 2);
        }
    }
    int rofs = lid >> 2, cofs = (lid & 3) * 2;
    int r0 = px0 + wid * 16 + rofs;
#pragma unroll
    for (int ni = 0; ni < 4; ++ni) {
        int c = ni * 8 + cofs;
        if (c < 18) {
            float2 bo = *(const float2*)(b_off + c);
            *(float2*)(g_off + r0 * 18 + c) =
                make_float2(acc[ni][0] + bo.x, acc[ni][1] + bo.y);
            *(float2*)(g_off + (r0 + 8) * 18 + c) =
                make_float2(acc[ni][2] + bo.x, acc[ni][3] + bo.y);
        }
    }
}

// ---------------- main v3: pipelined sampling + HMMA, 128px x 128co -----------
#define M_ABUF 69632
#define M_LO   34816
#define M_BHI  139264
#define M_BLO  174080
#define M_TOT  208896
#define RSF    132

struct Samp {
    float4 v00, v01, v10, v11;
    float w00, w01, w10, w11;
    uint32_t off;
};

__device__ __forceinline__ void samp_issue(Samp& S, int s, int t, int ky, int kx,
                                           int px0, int wid, int lid) {
    int p = s * 16 + wid;
    int px = px0 + p;
    int b = px >> 14, h = (px >> 7) & 127, w = px & 127;
    float2 d = *(const float2*)(g_off + px * 18 + 2 * t);
    float ysf = (float)(h - 1 + ky) + d.x;
    float xsf = (float)(w - 1 + kx) + d.y;
    float fy = floorf(ysf), fx = floorf(xsf);
    float wy = ysf - fy, wx = xsf - fx;
    int iy0 = (int)fy, ix0 = (int)fx;
    int iy1 = iy0 + 1, ix1 = ix0 + 1;
    float my0 = (iy0 >= 0 && iy0 < H_) ? 1.f : 0.f;
    float my1 = (iy1 >= 0 && iy1 < H_) ? 1.f : 0.f;
    float mx0 = (ix0 >= 0 && ix0 < W_) ? 1.f : 0.f;
    float mx1 = (ix1 >= 0 && ix1 < W_) ? 1.f : 0.f;
    int cy0 = min(H_ - 1, max(0, iy0)), cy1 = min(H_ - 1, max(0, iy1));
    int cx0 = min(W_ - 1, max(0, ix0)), cx1 = min(W_ - 1, max(0, ix1));
    int base = b * HW_;
    int c4 = lid * 4;
    S.v00 = *(const float4*)(g_x_nhwc + (base + cy0 * W_ + cx0) * CI_ + c4);
    S.v01 = *(const float4*)(g_x_nhwc + (base + cy0 * W_ + cx1) * CI_ + c4);
    S.v10 = *(const float4*)(g_x_nhwc + (base + cy1 * W_ + cx0) * CI_ + c4);
    S.v11 = *(const float4*)(g_x_nhwc + (base + cy1 * W_ + cx1) * CI_ + c4);
    S.w00 = (1.f - wy) * (1.f - wx) * my0 * mx0;
    S.w01 = (1.f - wy) * wx * my0 * mx1;
    S.w10 = wy * (1.f - wx) * my1 * mx0;
    S.w11 = wy * wx * my1 * mx1;
    S.off = (uint32_t)p * RS + (uint32_t)lid * 8;
}

__device__ __forceinline__ void samp_store(char* sb, uint32_t abase, const Samp& S) {
    float4 s;
    s.x = fmaf(S.v11.x, S.w11, fmaf(S.v10.x, S.w10, fmaf(S.v01.x, S.w01, S.v00.x * S.w00)));
    s.y = fmaf(S.v11.y, S.w11, fmaf(S.v10.y, S.w10, fmaf(S.v01.y, S.w01, S.v00.y * S.w00)));
    s.z = fmaf(S.v11.z, S.w11, fmaf(S.v10.z, S.w10, fmaf(S.v01.z, S.w01, S.v00.z * S.w00)));
    s.w = fmaf(S.v11.w, S.w11, fmaf(S.v10.w, S.w10, fmaf(S.v01.w, S.w01, S.v00.w * S.w00)));
    uint2 hp, lp;
    split4(s, hp, lp);
    *(uint2*)(sb + abase + S.off) = hp;
    *(uint2*)(sb + abase + M_LO + S.off) = lp;
}

__device__ __forceinline__ void copy_B(uint32_t sbase, int k, int tid) {
#pragma unroll
    for (int j = 0; j < 4; ++j) {
        int ch = tid + j * 512;
        int row = ch >> 4, c16 = ch & 15;
        uint32_t dof = (uint32_t)row * RS + (uint32_t)c16 * 16;
        uint32_t sof = (uint32_t)k * 32768 + (uint32_t)row * 256 + (uint32_t)c16 * 16;
        cp16(sbase + M_BHI + dof, (const char*)g_wb_hi + sof);
        cp16(sbase + M_BLO + dof, (const char*)g_wb_lo + sof);
    }
    cp_commit();
}

__global__ void __launch_bounds__(512, 1) k_main3() {
    extern __shared__ char sb[];
    uint32_t sbase = smem_u32(sb);

    int tid = threadIdx.x;
    int wid = tid >> 5, lid = tid & 31;
    int wm = wid >> 2, wn = wid & 3;
    int px0 = blockIdx.x * 128;

    float acc[2][4][4];
#pragma unroll
    for (int mi = 0; mi < 2; ++mi)
#pragma unroll
        for (int ni = 0; ni < 4; ++ni)
#pragma unroll
            for (int j = 0; j < 4; ++j) acc[mi][ni][j] = 0.f;

    uint32_t a_lane = (uint32_t)(wm * 32 + (lid & 15)) * RS + ((lid >> 4) << 4);
    uint32_t b_lane4 = (uint32_t)(wn * 32 + ((lid & 7) | ((lid >> 4) << 3))) * RS
                     + (((lid >> 3) & 1) << 4);

    // prologue: B[0] in flight, sample tap 0 into A buf 0
    copy_B(sbase, 0, tid);
    {
        Samp S;
#pragma unroll
        for (int s = 0; s < 8; ++s) {
            samp_issue(S, s, 0, 0, 0, px0, wid, lid);
            samp_store(sb, 0, S);
        }
    }
    cp_wait0();

    for (int k = 0; k < 9; ++k) {
        __syncthreads();
        if (k >= 1) { copy_B(sbase, k, tid); cp_wait0(); }
        __syncthreads();
        uint32_t Acur = (uint32_t)(k & 1) * M_ABUF;
        uint32_t Anxt = (uint32_t)((k & 1) ^ 1) * M_ABUF;
        int t = k + 1;
        int ky = t / 3, kx = t - ky * 3;
        bool samp = (k < 8);
        Samp S;
#pragma unroll
        for (int s = 0; s < 8; ++s) {
            if (samp) samp_issue(S, s, t, ky, kx, px0, wid, lid);
            {
                uint32_t kb = (uint32_t)s * 32;
                uint32_t bh4[2][4], bl4[2][4], ah[2][4], al[2][4];
#pragma unroll
                for (int ni2 = 0; ni2 < 2; ++ni2) {
                    uint32_t ba = b_lane4 + (uint32_t)(ni2 * 16) * RS + kb;
                    ldm_x4(bh4[ni2], sbase + M_BHI + ba);
                    ldm_x4(bl4[ni2], sbase + M_BLO + ba);
                }
#pragma unroll
                for (int mi = 0; mi < 2; ++mi) {
                    uint32_t aa = Acur + a_lane + (uint32_t)(mi * 16) * RS + kb;
                    ldm_x4(ah[mi], sbase + aa);
                    ldm_x4(al[mi], sbase + aa + M_LO);
                }
                // pass-major: 8x hh, 8x hl, 8x lh — same-acc distance = 8
#pragma unroll
                for (int mi = 0; mi < 2; ++mi)
#pragma unroll
                    for (int ni2 = 0; ni2 < 2; ++ni2)
#pragma unroll
                        for (int half = 0; half < 2; ++half)
                            mma_bf16(acc[mi][ni2 * 2 + half], ah[mi], bh4[ni2] + half * 2);
#pragma unroll
                for (int mi = 0; mi < 2; ++mi)
#pragma unroll
                    for (int ni2 = 0; ni2 < 2; ++ni2)
#pragma unroll
                        for (int half = 0; half < 2; ++half)
                            mma_bf16(acc[mi][ni2 * 2 + half], ah[mi], bl4[ni2] + half * 2);
#pragma unroll
                for (int mi = 0; mi < 2; ++mi)
#pragma unroll
                    for (int ni2 = 0; ni2 < 2; ++ni2)
#pragma unroll
                        for (int half = 0; half < 2; ++half)
                            mma_bf16(acc[mi][ni2 * 2 + half], al[mi], bh4[ni2] + half * 2);
            }
            if (samp) samp_store(sb, Anxt, S);
        }
    }

    // epilogue: stage to smem, coalesced store, BN partials
    __syncthreads();
    float* stg = (float*)sb;
    int rofs = lid >> 2, cofs = (lid & 3) * 2;
#pragma unroll
    for (int mi = 0; mi < 2; ++mi) {
        int r0 = wm * 32 + mi * 16 + rofs;
#pragma unroll
        for (int ni = 0; ni < 4; ++ni) {
            int co = wn * 32 + ni * 8 + cofs;
            *(float2*)(stg + r0 * RSF + co)       = make_float2(acc[mi][ni][0], acc[mi][ni][1]);
            *(float2*)(stg + (r0 + 8) * RSF + co) = make_float2(acc[mi][ni][2], acc[mi][ni][3]);
        }
    }
    __syncthreads();
#pragma unroll
    for (int tt = 0; tt < 8; ++tt) {
        int idx = tid + tt * 512;
        int row = idx >> 5, c4 = (idx & 31) * 4;
        float4 v = *(const float4*)(stg + row * RSF + c4);
        *(float4*)(g_out + (px0 + row) * CO_ + c4) = v;
    }
    {
        int co = tid & 127, q = tid >> 7;
        float s = 0.f, qq = 0.f;
#pragma unroll
        for (int r = 0; r < 32; ++r) {
            float v = stg[(q * 32 + r) * RSF + co];
            s += v; qq = fmaf(v, v, qq);
        }
        float* reds = (float*)(sb + M_BHI);
        float* redq = reds + 512;
        reds[q * 128 + co] = s;
        redq[q * 128 + co] = qq;
        __syncthreads();
        if (tid < 128) {
            float ss = reds[tid] + reds[128 + tid] + reds[256 + tid] + reds[384 + tid];
            float sq = redq[tid] + redq[128 + tid] + redq[256 + tid] + redq[384 + tid];
            atomicAdd(&g_sum[tid], (double)ss);
            atomicAdd(&g_sumsq[tid], (double)sq);
        }
    }
}

// ---------------- BN finalize ----------------
__global__ void k_fin(const float* __restrict__ gamma, const float* __restrict__ beta) {
    int c = threadIdx.x;
    if (c < CO_) {
        double N = (double)NPIX;
        double mean = g_sum[c] / N;
        double var  = g_sumsq[c] / N - mean * mean;
        float a = gamma[c] * rsqrtf((float)var + BN_EPS);
        g_scale[c] = a;
        g_shift[c] = beta[c] - (float)mean * a;
    }
}

// ---------------- apply BN + ReLU + transpose [px][co] -> NCHW ----------------
__global__ void k_apply(float* __restrict__ out) {
    __shared__ float sm[32][33];
    int b = blockIdx.z, co0 = blockIdx.y * 32, hw0 = blockIdx.x * 32;
    int tx = threadIdx.x, ty = threadIdx.y;
#pragma unroll
    for (int i = 0; i < 4; ++i) {
        int hw = hw0 + ty + i * 8;
        sm[ty + i * 8][tx] = g_out[(b * HW_ + hw) * CO_ + co0 + tx];
    }
    __syncthreads();
#pragma unroll
    for (int i = 0; i < 4; ++i) {
        int co = co0 + ty + i * 8;
        float a = g_scale[co], sh = g_shift[co];
        float v = fmaf(sm[tx][ty + i * 8], a, sh);
        out[(b * CO_ + co) * HW_ + hw0 + tx] = fmaxf(v, 0.f);
    }
}

// ---------------- launch ----------------
extern "C" void kernel_launch(void* const* d_in, const int* in_sizes, int n_in,
                              void* d_out, int out_size) {
    const float* x      = (const float*)d_in[0];
    const float* w_off  = (const float*)d_in[1];
    const float* b_off  = (const float*)d_in[2];
    const float* w_dcn  = (const float*)d_in[3];
    const float* gamma  = (const float*)d_in[4];
    const float* beta   = (const float*)d_in[5];
    float* out = (float*)d_out;

    cudaFuncSetAttribute(k_offT,  cudaFuncAttributeMaxDynamicSharedMemorySize, OFF_TOT);
    cudaFuncSetAttribute(k_main3, cudaFuncAttributeMaxDynamicSharedMemorySize, M_TOT);

    dim3 tb(32, 8);
    k_tr_x<<<dim3(512, 4, B_), tb>>>(x);          // launch 0
    k_prep<<<576, 256>>>(w_dcn, w_off);           // launch 1
    k_offT<<<512, 256, OFF_TOT>>>(b_off);         // launch 2
    k_main3<<<512, 512, M_TOT>>>();               // launch 3  <- ncu capture slot
    k_fin<<<1, 128>>>(gamma, beta);               // launch 4
    k_apply<<<dim3(512, 4, B_), tb>>>(out);       // launch 5
}

// round 8
// speedup vs baseline: 1.9820x; 1.0625x over previous
#include <cuda_runtime.h>
#include <cuda_bf16.h>
#include <cstdint>

#define B_   4
#define CI_  128
#define CO_  128
#define H_   128
#define W_   128
#define HW_  (H_*W_)
#define KK_  9
#define NPIX (B_*HW_)   // 65536
#define BN_EPS 0.001f

// ---------------- scratch ----------------
__device__ float  g_x_nhwc[NPIX*CI_];                          // [b][h][w][ci]
__device__ float  g_off[NPIX*18];                              // [px][18]
__device__ __align__(16) __nv_bfloat16 g_wb_hi[KK_*CO_*CI_];   // [tap][co][ci]
__device__ __align__(16) __nv_bfloat16 g_wb_lo[KK_*CO_*CI_];
__device__ __align__(16) __nv_bfloat16 g_wo_hi[KK_*32*CI_];    // offset conv w
__device__ __align__(16) __nv_bfloat16 g_wo_lo[KK_*32*CI_];
__device__ float  g_out[NPIX*CO_];                             // [px][co]
__device__ double g_sum[CO_];
__device__ double g_sumsq[CO_];
__device__ float  g_scale[CO_];
__device__ float  g_shift[CO_];

__device__ __forceinline__ uint32_t smem_u32(const void* p) {
    uint32_t a;
    asm("{ .reg .u64 t; cvta.to.shared.u64 t, %1; cvt.u32.u64 %0, t; }" : "=r"(a) : "l"(p));
    return a;
}
__device__ __forceinline__ void ldm_x4(uint32_t* r, uint32_t a) {
    asm volatile("ldmatrix.sync.aligned.m8n8.x4.shared.b16 {%0,%1,%2,%3}, [%4];"
                 : "=r"(r[0]), "=r"(r[1]), "=r"(r[2]), "=r"(r[3]) : "r"(a));
}
__device__ __forceinline__ void mma_bf16(float* c, const uint32_t* a, const uint32_t* b) {
    asm volatile(
        "mma.sync.aligned.m16n8k16.row.col.f32.bf16.bf16.f32 "
        "{%0,%1,%2,%3}, {%4,%5,%6,%7}, {%8,%9}, {%0,%1,%2,%3};"
        : "+f"(c[0]), "+f"(c[1]), "+f"(c[2]), "+f"(c[3])
        : "r"(a[0]), "r"(a[1]), "r"(a[2]), "r"(a[3]), "r"(b[0]), "r"(b[1]));
}
__device__ __forceinline__ void bf16_split(float v, uint16_t& h, uint16_t& l) {
    __nv_bfloat16 hb = __float2bfloat16(v);
    __nv_bfloat16 lb = __float2bfloat16(v - __bfloat162float(hb));
    h = __bfloat16_as_ushort(hb);
    l = __bfloat16_as_ushort(lb);
}
__device__ __forceinline__ uint32_t prmt_hi(uint32_t a, uint32_t b) {
    uint32_t d;
    asm("prmt.b32 %0, %1, %2, 0x7632;" : "=r"(d) : "r"(a), "r"(b));
    return d;
}
__device__ __forceinline__ void split4(float4 s, uint2& hp, uint2& lp) {
    uint32_t u0 = __float_as_uint(s.x), u1 = __float_as_uint(s.y);
    uint32_t u2 = __float_as_uint(s.z), u3 = __float_as_uint(s.w);
    hp.x = prmt_hi(u0, u1);
    hp.y = prmt_hi(u2, u3);
    float l0 = s.x - __uint_as_float(u0 & 0xFFFF0000u);
    float l1 = s.y - __uint_as_float(u1 & 0xFFFF0000u);
    float l2 = s.z - __uint_as_float(u2 & 0xFFFF0000u);
    float l3 = s.w - __uint_as_float(u3 & 0xFFFF0000u);
    lp.x = prmt_hi(__float_as_uint(l0), __float_as_uint(l1));
    lp.y = prmt_hi(__float_as_uint(l2), __float_as_uint(l3));
}
__device__ __forceinline__ void cp16(uint32_t dst, const void* src) {
    asm volatile("cp.async.cg.shared.global [%0], [%1], 16;" :: "r"(dst), "l"(src));
}
__device__ __forceinline__ void cp_commit() { asm volatile("cp.async.commit_group;" ::: "memory"); }
__device__ __forceinline__ void cp_wait0()  { asm volatile("cp.async.wait_group 0;" ::: "memory"); }
#define BAR_SYNC(id)   asm volatile("bar.sync %0, 512;"   :: "r"(id) : "memory")
#define BAR_ARRIVE(id) asm volatile("bar.arrive %0, 512;" :: "r"(id) : "memory")

// ---------------- x: NCHW -> NHWC ----------------
__global__ void k_tr_x(const float* __restrict__ x) {
    __shared__ float sm[32][33];
    int b = blockIdx.z, ci0 = blockIdx.y * 32, hw0 = blockIdx.x * 32;
    int tx = threadIdx.x, ty = threadIdx.y;
#pragma unroll
    for (int i = 0; i < 4; ++i) {
        int ci = ci0 + ty + i * 8;
        sm[ty + i * 8][tx] = x[(b * CI_ + ci) * HW_ + hw0 + tx];
    }
    __syncthreads();
#pragma unroll
    for (int i = 0; i < 4; ++i) {
        int hw = hw0 + ty + i * 8;
        g_x_nhwc[(b * HW_ + hw) * CI_ + ci0 + tx] = sm[tx][ty + i * 8];
    }
}

// ---------------- prep: BN zero + both weight transforms ----------------
__global__ void k_prep(const float* __restrict__ w_dcn, const float* __restrict__ w_off) {
    int idx = blockIdx.x * 256 + threadIdx.x;
    if (idx < 128) { g_sum[idx] = 0.0; g_sumsq[idx] = 0.0; }
    if (idx < KK_ * CO_ * CI_) {
        int tap = idx >> 14;
        int r   = idx & 16383;
        int co  = r >> 7;
        int ci  = r & 127;
        float w = w_dcn[(co * CI_ + ci) * KK_ + tap];
        uint16_t h, l;
        bf16_split(w, h, l);
        g_wb_hi[idx] = __ushort_as_bfloat16(h);
        g_wb_lo[idx] = __ushort_as_bfloat16(l);
    }
    if (idx < KK_ * 32 * CI_) {
        int tap = idx >> 12;
        int r   = idx & 4095;
        int co  = r >> 7;
        int ci  = r & 127;
        float w = (co < 18) ? w_off[(co * CI_ + ci) * KK_ + tap] : 0.f;
        uint16_t h, l;
        bf16_split(w, h, l);
        g_wo_hi[idx] = __ushort_as_bfloat16(h);
        g_wo_lo[idx] = __ushort_as_bfloat16(l);
    }
}

#define RS 272   // padded stride for k_offT only

// ---------------- offset conv, tensorized (unchanged) ----------------
#define OFF_AHI 0
#define OFF_ALO 34816
#define OFF_BHI 69632
#define OFF_BLO 78336
#define OFF_TOT 87040

__device__ __forceinline__ void ldm_x2(uint32_t* r, uint32_t a) {
    asm volatile("ldmatrix.sync.aligned.m8n8.x2.shared.b16 {%0,%1}, [%2];"
                 : "=r"(r[0]), "=r"(r[1]) : "r"(a));
}

__global__ void __launch_bounds__(256, 2) k_offT(const float* __restrict__ b_off) {
    extern __shared__ char sb[];
    uint32_t sbase = smem_u32(sb);
    int tid = threadIdx.x;
    int wid = tid >> 5, lid = tid & 31;
    int px0 = blockIdx.x * 128;

    float acc[4][4];
#pragma unroll
    for (int ni = 0; ni < 4; ++ni)
#pragma unroll
        for (int j = 0; j < 4; ++j) acc[ni][j] = 0.f;

    uint32_t a_lane = (uint32_t)(wid * 16 + (lid & 15)) * RS + ((lid >> 4) << 4);
    uint32_t b_lane4 = (uint32_t)((lid & 7) | ((lid >> 4) << 3)) * RS + (((lid >> 3) & 1) << 4);

    for (int k = 0; k < 9; ++k) {
        int ky = k / 3, kx = k - ky * 3;
        __syncthreads();
#pragma unroll
        for (int t = 0; t < 2; ++t) {
            int e = tid + t * 256;
            int row = e >> 4, c16 = e & 15;
            *(uint4*)(sb + OFF_BHI + row * RS + c16 * 16) =
                *(const uint4*)(g_wo_hi + k * 4096 + row * 128 + c16 * 8);
            *(uint4*)(sb + OFF_BLO + row * RS + c16 * 16) =
                *(const uint4*)(g_wo_lo + k * 4096 + row * 128 + c16 * 8);
        }
#pragma unroll 2
        for (int i = 0; i < 16; ++i) {
            int p = i * 8 + wid;
            int px = px0 + p;
            int b = px >> 14, h = (px >> 7) & 127, w = px & 127;
            int y = h - 1 + ky, xx = w - 1 + kx;
            uint2 hp = make_uint2(0u, 0u), lp = make_uint2(0u, 0u);
            if ((unsigned)y < (unsigned)H_ && (unsigned)xx < (unsigned)W_) {
                float4 v = *(const float4*)(g_x_nhwc + ((b * H_ + y) * W_ + xx) * CI_ + lid * 4);
                split4(v, hp, lp);
            }
            uint32_t off = (uint32_t)p * RS + (uint32_t)lid * 8;
            *(uint2*)(sb + OFF_AHI + off) = hp;
            *(uint2*)(sb + OFF_ALO + off) = lp;
        }
        __syncthreads();
#pragma unroll
        for (int ks = 0; ks < 8; ++ks) {
            uint32_t kb = (uint32_t)ks * 32;
            uint32_t ah[4], al[4], bh4[2][4], bl4[2][4];
            ldm_x4(ah, sbase + OFF_AHI + a_lane + kb);
            ldm_x4(al, sbase + OFF_ALO + a_lane + kb);
#pragma unroll
            for (int ni2 = 0; ni2 < 2; ++ni2) {
                uint32_t ba = b_lane4 + (uint32_t)(ni2 * 16) * RS + kb;
                ldm_x4(bh4[ni2], sbase + OFF_BHI + ba);
                ldm_x4(bl4[ni2], sbase + OFF_BLO + ba);
            }
#pragma unroll
            for (int ni2 = 0; ni2 < 2; ++ni2)
#pragma unroll
                for (int half = 0; half < 2; ++half)
                    mma_bf16(acc[ni2 * 2 + half], ah, bh4[ni2] + half * 2);
#pragma unroll
            for (int ni2 = 0; ni2 < 2; ++ni2)
#pragma unroll
                for (int half = 0; half < 2; ++half)
                    mma_bf16(acc[ni2 * 2 + half], ah, bl4[ni2] + half * 2);
#pragma unroll
            for (int ni2 = 0; ni2 < 2; ++ni2)
#pragma unroll
                for (int half = 0; half < 2; ++half)
                    mma_bf16(acc[ni2 * 2 + half], al, bh4[ni2] + half * 2);
        }
    }
    int rofs = lid >> 2, cofs = (lid & 3) * 2;
    int r0 = px0 + wid * 16 + rofs;
#pragma unroll
    for (int ni = 0; ni < 4; ++ni) {
        int c = ni * 8 + cofs;
        if (c < 18) {
            float2 bo = *(const float2*)(b_off + c);
            *(float2*)(g_off + r0 * 18 + c) =
                make_float2(acc[ni][0] + bo.x, acc[ni][1] + bo.y);
            *(float2*)(g_off + (r0 + 8) * 18 + c) =
                make_float2(acc[ni][2] + bo.x, acc[ni][3] + bo.y);
        }
    }
}

// ---------------- main: warp-specialized producer/consumer ----------------
// smem layout (XOR-swizzled 256B rows):
//   A stage s (s=0,1): s*65536   (hi +0, lo +32768)        -> 128KB
//   B-hi stage s:      131072 + s*32768                    -> 64KB
//   B-lo (single):     196608                               -> 32KB
// total 229376 B. Barriers: A_FULL 1,2  A_FREE 3,4  BLO_FULL 5  BLO_FREE 6
#define A_ST(s)   ((uint32_t)(s) * 65536u)
#define A_LOOFF   32768u
#define BHI_ST(s) (131072u + (uint32_t)(s) * 32768u)
#define BLO_ST    196608u
#define WS_TOT    229376
#define RSF       132

struct Samp {
    float4 v00, v01, v10, v11;
    float w00, w01, w10, w11;
    uint32_t off;
};

__device__ __forceinline__ void samp_issueP(Samp& S, int p, int t, int ky, int kx,
                                            int px0, int lid) {
    int px = px0 + p;
    int b = px >> 14, h = (px >> 7) & 127, w = px & 127;
    float2 d = *(const float2*)(g_off + px * 18 + 2 * t);
    float ysf = (float)(h - 1 + ky) + d.x;
    float xsf = (float)(w - 1 + kx) + d.y;
    float fy = floorf(ysf), fx = floorf(xsf);
    float wy = ysf - fy, wx = xsf - fx;
    int iy0 = (int)fy, ix0 = (int)fx;
    int iy1 = iy0 + 1, ix1 = ix0 + 1;
    float my0 = (iy0 >= 0 && iy0 < H_) ? 1.f : 0.f;
    float my1 = (iy1 >= 0 && iy1 < H_) ? 1.f : 0.f;
    float mx0 = (ix0 >= 0 && ix0 < W_) ? 1.f : 0.f;
    float mx1 = (ix1 >= 0 && ix1 < W_) ? 1.f : 0.f;
    int cy0 = min(H_ - 1, max(0, iy0)), cy1 = min(H_ - 1, max(0, iy1));
    int cx0 = min(W_ - 1, max(0, ix0)), cx1 = min(W_ - 1, max(0, ix1));
    int base = b * HW_;
    int c4 = lid * 4;
    S.v00 = *(const float4*)(g_x_nhwc + (base + cy0 * W_ + cx0) * CI_ + c4);
    S.v01 = *(const float4*)(g_x_nhwc + (base + cy0 * W_ + cx1) * CI_ + c4);
    S.v10 = *(const float4*)(g_x_nhwc + (base + cy1 * W_ + cx0) * CI_ + c4);
    S.v11 = *(const float4*)(g_x_nhwc + (base + cy1 * W_ + cx1) * CI_ + c4);
    S.w00 = (1.f - wy) * (1.f - wx) * my0 * mx0;
    S.w01 = (1.f - wy) * wx * my0 * mx1;
    S.w10 = wy * (1.f - wx) * my1 * mx0;
    S.w11 = wy * wx * my1 * mx1;
    S.off = (uint32_t)p * 256u + (((((uint32_t)lid >> 1) ^ ((uint32_t)p & 7u)) << 4) | (((uint32_t)lid & 1u) << 3));
}

__device__ __forceinline__ void samp_storeP(char* sb, uint32_t abase, const Samp& S) {
    float4 s;
    s.x = fmaf(S.v11.x, S.w11, fmaf(S.v10.x, S.w10, fmaf(S.v01.x, S.w01, S.v00.x * S.w00)));
    s.y = fmaf(S.v11.y, S.w11, fmaf(S.v10.y, S.w10, fmaf(S.v01.y, S.w01, S.v00.y * S.w00)));
    s.z = fmaf(S.v11.z, S.w11, fmaf(S.v10.z, S.w10, fmaf(S.v01.z, S.w01, S.v00.z * S.w00)));
    s.w = fmaf(S.v11.w, S.w11, fmaf(S.v10.w, S.w10, fmaf(S.v01.w, S.w01, S.v00.w * S.w00)));
    uint2 hp, lp;
    split4(s, hp, lp);
    *(uint2*)(sb + abase + S.off) = hp;
    *(uint2*)(sb + abase + A_LOOFF + S.off) = lp;
}

// swizzled cp.async of one 32KB B tile (8 chunks per thread, 256 prod threads)
__device__ __forceinline__ void copy_B_swz(uint32_t dstbase, const char* src, int ptid) {
#pragma unroll
    for (int j = 0; j < 8; ++j) {
        int c = ptid + j * 256;
        uint32_t row = (uint32_t)(c >> 4), c16 = (uint32_t)(c & 15);
        uint32_t dof = row * 256u + ((c16 ^ (row & 7u)) << 4);
        cp16(dstbase + dof, src + c * 16);
    }
}

__global__ void __launch_bounds__(512, 1) k_mainWS() {
    extern __shared__ char sb[];
    uint32_t sbase = smem_u32(sb);
    int tid = threadIdx.x;
    int wid = tid >> 5, lid = tid & 31;
    int px0 = blockIdx.x * 128;

    float acc[2][8][4];
#pragma unroll
    for (int mi = 0; mi < 2; ++mi)
#pragma unroll
        for (int nf = 0; nf < 8; ++nf)
#pragma unroll
            for (int j = 0; j < 4; ++j) acc[mi][nf][j] = 0.f;

    if (wid < 8) {
        // ================= CONSUMER =================
        int mw = wid >> 1, nw = wid & 1;
        uint32_t rA[2], rA7[2];
#pragma unroll
        for (int mi = 0; mi < 2; ++mi) {
            uint32_t r = (uint32_t)(mw * 32 + mi * 16 + (lid & 15));
            rA[mi] = r * 256u; rA7[mi] = r & 7u;
        }
        uint32_t chAh = (uint32_t)(lid >> 4);
        uint32_t rowp = (uint32_t)((lid & 7) | ((lid >> 4) << 3));
        uint32_t chBh = (uint32_t)((lid >> 3) & 1);
        uint32_t rB[4], rB7[4];
#pragma unroll
        for (int n = 0; n < 4; ++n) {
            uint32_t r = (uint32_t)(nw * 64 + n * 16) + rowp;
            rB[n] = r * 256u; rB7[n] = r & 7u;
        }

        for (int k = 0; k < 9; ++k) {
            BAR_SYNC(1 + (k & 1));     // A[k] + Bhi[k] ready
            BAR_SYNC(5);               // Blo[k] ready
            uint32_t Ast = sbase + A_ST(k & 1);
            uint32_t Bh  = sbase + BHI_ST(k & 1);
            uint32_t Bl  = sbase + BLO_ST;
#pragma unroll
            for (int s = 0; s < 8; ++s) {
                uint32_t cA = (uint32_t)(2 * s) + chAh;
                uint32_t cB = (uint32_t)(2 * s) + chBh;
                uint32_t ah[2][4], bh[4][4], bl[4][4];
#pragma unroll
                for (int mi = 0; mi < 2; ++mi)
                    ldm_x4(ah[mi], Ast + rA[mi] + ((cA ^ rA7[mi]) << 4));
#pragma unroll
                for (int n = 0; n < 4; ++n)
                    ldm_x4(bh[n], Bh + rB[n] + ((cB ^ rB7[n]) << 4));
#pragma unroll
                for (int n = 0; n < 4; ++n)
                    ldm_x4(bl[n], Bl + rB[n] + ((cB ^ rB7[n]) << 4));
                // pass hh
#pragma unroll
                for (int mi = 0; mi < 2; ++mi)
#pragma unroll
                    for (int nf = 0; nf < 8; ++nf)
                        mma_bf16(acc[mi][nf], ah[mi], bh[nf >> 1] + (nf & 1) * 2);
                // pass hl
#pragma unroll
                for (int mi = 0; mi < 2; ++mi)
#pragma unroll
                    for (int nf = 0; nf < 8; ++nf)
                        mma_bf16(acc[mi][nf], ah[mi], bl[nf >> 1] + (nf & 1) * 2);
                // pass lh (load al late to cap liveness)
                uint32_t al[2][4];
#pragma unroll
                for (int mi = 0; mi < 2; ++mi)
                    ldm_x4(al[mi], Ast + A_LOOFF + rA[mi] + ((cA ^ rA7[mi]) << 4));
#pragma unroll
                for (int mi = 0; mi < 2; ++mi)
#pragma unroll
                    for (int nf = 0; nf < 8; ++nf)
                        mma_bf16(acc[mi][nf], al[mi], bh[nf >> 1] + (nf & 1) * 2);
            }
            BAR_ARRIVE(6);             // Blo free
            BAR_ARRIVE(3 + (k & 1));   // A stage free
        }
    } else {
        // ================= PRODUCER =================
        int wp = wid - 8;
        int ptid = wp * 32 + lid;
        for (int k = 0; k < 9; ++k) {
            int st = k & 1;
            if (k >= 2) BAR_SYNC(3 + st);
            // B-hi[k] prefetch
            copy_B_swz(sbase + BHI_ST(st), (const char*)g_wb_hi + k * 32768, ptid);
            cp_commit();
            // sample 16 pixels into A stage (depth-1 pipelined)
            int ky = k / 3, kx = k - ky * 3;
            uint32_t Ast = A_ST(st);
            Samp S0, S1;
            samp_issueP(S0, wp, k, ky, kx, px0, lid);
#pragma unroll
            for (int i = 0; i < 16; ++i) {
                if ((i & 1) == 0) {
                    if (i < 15) samp_issueP(S1, (i + 1) * 8 + wp, k, ky, kx, px0, lid);
                    samp_storeP(sb, Ast, S0);
                } else {
                    if (i < 15) samp_issueP(S0, (i + 1) * 8 + wp, k, ky, kx, px0, lid);
                    samp_storeP(sb, Ast, S1);
                }
            }
            cp_wait0();
            __threadfence_block();
            BAR_ARRIVE(1 + st);        // A[k] + Bhi[k] full
            if (k >= 1) BAR_SYNC(6);   // Blo buffer free
            copy_B_swz(sbase + BLO_ST, (const char*)g_wb_lo + k * 32768, ptid);
            cp_commit();
            cp_wait0();
            BAR_ARRIVE(5);             // Blo[k] full
        }
    }

    __syncthreads();
    // ---- epilogue: consumers stage acc (A region is free) ----
    float* stg = (float*)sb;
    if (wid < 8) {
        int mw = wid >> 1, nw = wid & 1;
        int rofs = lid >> 2, cofs = (lid & 3) * 2;
#pragma unroll
        for (int mi = 0; mi < 2; ++mi) {
            int r0 = mw * 32 + mi * 16 + rofs;
#pragma unroll
            for (int nf = 0; nf < 8; ++nf) {
                int co = nw * 64 + nf * 8 + cofs;
                *(float2*)(stg + r0 * RSF + co)       = make_float2(acc[mi][nf][0], acc[mi][nf][1]);
                *(float2*)(stg + (r0 + 8) * RSF + co) = make_float2(acc[mi][nf][2], acc[mi][nf][3]);
            }
        }
    }
    __syncthreads();
#pragma unroll
    for (int tt = 0; tt < 8; ++tt) {
        int idx = tid + tt * 512;
        int row = idx >> 5, c4 = (idx & 31) * 4;
        float4 v = *(const float4*)(stg + row * RSF + c4);
        *(float4*)(g_out + (px0 + row) * CO_ + c4) = v;
    }
    {
        int co = tid & 127, q = tid >> 7;
        float s = 0.f, qq = 0.f;
#pragma unroll
        for (int r = 0; r < 32; ++r) {
            float v = stg[(q * 32 + r) * RSF + co];
            s += v; qq = fmaf(v, v, qq);
        }
        float* reds = (float*)(sb + BHI_ST(0));
        float* redq = reds + 512;
        reds[q * 128 + co] = s;
        redq[q * 128 + co] = qq;
        __syncthreads();
        if (tid < 128) {
            float ss = reds[tid] + reds[128 + tid] + reds[256 + tid] + reds[384 + tid];
            float sq = redq[tid] + redq[128 + tid] + redq[256 + tid] + redq[384 + tid];
            atomicAdd(&g_sum[tid], (double)ss);
            atomicAdd(&g_sumsq[tid], (double)sq);
        }
    }
}

// ---------------- BN finalize ----------------
__global__ void k_fin(const float* __restrict__ gamma, const float* __restrict__ beta) {
    int c = threadIdx.x;
    if (c < CO_) {
        double N = (double)NPIX;
        double mean = g_sum[c] / N;
        double var  = g_sumsq[c] / N - mean * mean;
        float a = gamma[c] * rsqrtf((float)var + BN_EPS);
        g_scale[c] = a;
        g_shift[c] = beta[c] - (float)mean * a;
    }
}

// ---------------- apply BN + ReLU + transpose [px][co] -> NCHW ----------------
__global__ void k_apply(float* __restrict__ out) {
    __shared__ float sm[32][33];
    int b = blockIdx.z, co0 = blockIdx.y * 32, hw0 = blockIdx.x * 32;
    int tx = threadIdx.x, ty = threadIdx.y;
#pragma unroll
    for (int i = 0; i < 4; ++i) {
        int hw = hw0 + ty + i * 8;
        sm[ty + i * 8][tx] = g_out[(b * HW_ + hw) * CO_ + co0 + tx];
    }
    __syncthreads();
#pragma unroll
    for (int i = 0; i < 4; ++i) {
        int co = co0 + ty + i * 8;
        float a = g_scale[co], sh = g_shift[co];
        float v = fmaf(sm[tx][ty + i * 8], a, sh);
        out[(b * CO_ + co) * HW_ + hw0 + tx] = fmaxf(v, 0.f);
    }
}

// ---------------- launch ----------------
extern "C" void kernel_launch(void* const* d_in, const int* in_sizes, int n_in,
                              void* d_out, int out_size) {
    const float* x      = (const float*)d_in[0];
    const float* w_off  = (const float*)d_in[1];
    const float* b_off  = (const float*)d_in[2];
    const float* w_dcn  = (const float*)d_in[3];
    const float* gamma  = (const float*)d_in[4];
    const float* beta   = (const float*)d_in[5];
    float* out = (float*)d_out;

    cudaFuncSetAttribute(k_offT,   cudaFuncAttributeMaxDynamicSharedMemorySize, OFF_TOT);
    cudaFuncSetAttribute(k_mainWS, cudaFuncAttributeMaxDynamicSharedMemorySize, WS_TOT);

    dim3 tb(32, 8);
    k_tr_x<<<dim3(512, 4, B_), tb>>>(x);          // launch 0
    k_prep<<<576, 256>>>(w_dcn, w_off);           // launch 1
    k_offT<<<512, 256, OFF_TOT>>>(b_off);         // launch 2
    k_mainWS<<<512, 512, WS_TOT>>>();             // launch 3  <- ncu capture slot
    k_fin<<<1, 128>>>(gamma, beta);               // launch 4
    k_apply<<<dim3(512, 4, B_), tb>>>(out);       // launch 5
}